// round 12
// baseline (speedup 1.0000x reference)
#include <cuda_runtime.h>
#include <cuda_bf16.h>
#include <math.h>

// Problem constants
#define B_  16
#define N_  50
#define H_  128
#define V_  40000
#define VM1 39999      // V-1 rows of b_emb / output columns
#define R_  (B_*N_)    // 800 rows
#define NT_ 313        // ceil(VM1/128) vocab tiles (128 rows each)
#define KX  400        // padded Xcat/Wcat K (386 used)

// ---------------- scratch (static __device__, no allocs) ----------------
__device__ float g_hidden[R_*H_];
__device__ float g_Xcat  [R_*KX];      // [AHin(128) | AHout(128) | hidden(128) | rsin | rsout | pad]
__device__ float g_Wcat  [512*KX];
__device__ float g_bc    [512];
__device__ float g_T     [R_*512];
__device__ float g_q2qt  [R_*256];     // cols 0..127 = q2, cols 128..255 = qt
__device__ float g_a     [B_*H_];
// HMMA staging: bf16 hi/lo split, ldmatrix XOR-chunk swizzled layouts
__device__ unsigned char g_embh[(size_t)NT_*32768];
__device__ unsigned char g_embl[(size_t)NT_*32768];
__device__ unsigned char g_qbh [B_*16384];
__device__ unsigned char g_qbl [B_*16384];
__device__ int g_len[B_];

// ---------------- small helpers ----------------
__device__ __forceinline__ float sigmoidf_(float x){ return 1.f/(1.f+expf(-x)); }

__device__ __forceinline__ unsigned smem_u32(const void* p){
    unsigned a;
    asm("{ .reg .u64 t; cvta.to.shared.u64 t, %1; cvt.u32.u64 %0, t; }" : "=r"(a) : "l"(p));
    return a;
}
__device__ __forceinline__ unsigned long long pack2(float x, float y){
    unsigned long long r;
    asm("mov.b64 %0, {%1, %2};" : "=l"(r) : "f"(x), "f"(y));
    return r;
}
__device__ __forceinline__ unsigned long long fma2(unsigned long long a,
                                                   unsigned long long b,
                                                   unsigned long long c){
    unsigned long long d;
    asm("fma.rn.f32x2 %0, %1, %2, %3;" : "=l"(d) : "l"(a), "l"(b), "l"(c));
    return d;
}
__device__ __forceinline__ float lo2(unsigned long long u){
    return __uint_as_float((unsigned)(u & 0xffffffffULL));
}
__device__ __forceinline__ float hi2(unsigned long long u){
    return __uint_as_float((unsigned)(u >> 32));
}
__device__ __forceinline__ unsigned bf16pair(float a, float b){
    __nv_bfloat162 t = __floats2bfloat162_rn(a, b);
    return *reinterpret_cast<unsigned*>(&t);
}
__device__ __forceinline__ float bf16of(float x){
    return __bfloat162float(__float2bfloat16(x));
}
__device__ __forceinline__ void ldsm4(unsigned& r0, unsigned& r1, unsigned& r2, unsigned& r3,
                                      unsigned addr){
    asm volatile("ldmatrix.sync.aligned.m8n8.x4.shared.b16 {%0,%1,%2,%3}, [%4];"
                 : "=r"(r0),"=r"(r1),"=r"(r2),"=r"(r3) : "r"(addr));
}
__device__ __forceinline__ void mma16816(float* c, unsigned a0, unsigned a1, unsigned a2,
                                         unsigned a3, unsigned b0, unsigned b1){
    asm volatile(
        "mma.sync.aligned.m16n8k16.row.col.f32.bf16.bf16.f32 "
        "{%0,%1,%2,%3}, {%4,%5,%6,%7}, {%8,%9}, {%0,%1,%2,%3};"
        : "+f"(c[0]), "+f"(c[1]), "+f"(c[2]), "+f"(c[3])
        : "r"(a0), "r"(a1), "r"(a2), "r"(a3), "r"(b0), "r"(b1));
}

// ---------------- fast SGEMM: 128x64 tile, 256 threads, 8r x 4j per thread ----------------
// out[r,j] = sum_k X[r,k]*W[j,k] (+bias). W row j from W0 (j<Jsplit) or W1. K%16==0.
// (Round-9 configuration — measured fastest; 64x64 variant regressed.)
__global__ void __launch_bounds__(256)
k_gemm_f(const float* __restrict__ X, const float* __restrict__ W0,
         const float* __restrict__ W1, int Jsplit,
         const float* __restrict__ bias0, const float* __restrict__ bias1,
         float* __restrict__ out, int R, int K, int J){
    __shared__ __align__(16) float xs[16][132];
    __shared__ __align__(16) float ws[16][68];
    const int tid = threadIdx.x;
    const int tr = tid >> 4, tc = tid & 15;
    const int r0 = blockIdx.y << 7, j0 = blockIdx.x << 6;
    unsigned long long acc[4][4];
    #pragma unroll
    for (int p=0;p<4;p++)
        #pragma unroll
        for (int j=0;j<4;j++) acc[p][j] = 0ULL;

    for (int kc = 0; kc < K; kc += 16){
        // stage X chunk: 128 rows x 16 k (512 float4 loads)
        #pragma unroll
        for (int it = 0; it < 2; it++){
            int idx = tid + (it<<8);
            int rr = idx >> 2, kq = idx & 3;
            float4 v = make_float4(0.f,0.f,0.f,0.f);
            if (r0 + rr < R)
                v = *reinterpret_cast<const float4*>(X + (size_t)(r0+rr)*K + kc + (kq<<2));
            xs[(kq<<2)+0][rr] = v.x;
            xs[(kq<<2)+1][rr] = v.y;
            xs[(kq<<2)+2][rr] = v.z;
            xs[(kq<<2)+3][rr] = v.w;
        }
        // stage W chunk: 64 j x 16 k (256 float4 loads)
        {
            int jj = tid >> 2, kq = tid & 3;
            int j = j0 + jj;
            float4 v = make_float4(0.f,0.f,0.f,0.f);
            if (j < J){
                const float* Wr = (j < Jsplit) ? (W0 + (size_t)j*K)
                                               : (W1 + (size_t)(j-Jsplit)*K);
                v = *reinterpret_cast<const float4*>(Wr + kc + (kq<<2));
            }
            ws[(kq<<2)+0][jj] = v.x;
            ws[(kq<<2)+1][jj] = v.y;
            ws[(kq<<2)+2][jj] = v.z;
            ws[(kq<<2)+3][jj] = v.w;
        }
        __syncthreads();
        #pragma unroll
        for (int kk = 0; kk < 16; kk++){
            float4 xA = *reinterpret_cast<const float4*>(&xs[kk][tr<<3]);
            float4 xB = *reinterpret_cast<const float4*>(&xs[kk][(tr<<3)+4]);
            float4 wv = *reinterpret_cast<const float4*>(&ws[kk][tc<<2]);
            unsigned long long xu0 = pack2(xA.x, xA.y);
            unsigned long long xu1 = pack2(xA.z, xA.w);
            unsigned long long xu2 = pack2(xB.x, xB.y);
            unsigned long long xu3 = pack2(xB.z, xB.w);
            float wf[4] = {wv.x, wv.y, wv.z, wv.w};
            #pragma unroll
            for (int j = 0; j < 4; j++){
                unsigned long long wb = pack2(wf[j], wf[j]);
                acc[0][j] = fma2(xu0, wb, acc[0][j]);
                acc[1][j] = fma2(xu1, wb, acc[1][j]);
                acc[2][j] = fma2(xu2, wb, acc[2][j]);
                acc[3][j] = fma2(xu3, wb, acc[3][j]);
            }
        }
        __syncthreads();
    }
    #pragma unroll
    for (int p = 0; p < 4; p++){
        #pragma unroll
        for (int e = 0; e < 2; e++){
            int r = r0 + (tr<<3) + (p<<1) + e;
            if (r >= R) continue;
            #pragma unroll
            for (int j = 0; j < 4; j++){
                int jj = j0 + (tc<<2) + j;
                if (jj >= J) continue;
                float bv = (jj < Jsplit) ? (bias0 ? bias0[jj] : 0.f)
                                         : (bias1 ? bias1[jj - Jsplit] : 0.f);
                float val = e ? hi2(acc[p][j]) : lo2(acc[p][j]);
                out[(size_t)r*J + jj] = val + bv;
            }
        }
    }
}

// ---------------- prep A: WA/WB = w_ih halves @ W_ein/W_eout -> Wcat cols [0:256) ----------------
__global__ void k_prep_wa(const float* __restrict__ w_ih, const float* __restrict__ W_ein,
                          const float* __restrict__ W_eout){
    __shared__ float xs1[16][65], xs2[16][65];
    __shared__ float ws1[16][65], ws2[16][65];
    int tid = threadIdx.x;
    int tr = tid >> 4, tc = tid & 15;
    int j0 = blockIdx.y << 6, h0 = blockIdx.x << 6;
    float acc1[4][4] = {}, acc2[4][4] = {};
    for (int kc = 0; kc < H_; kc += 16){
        for (int t = tid; t < 1024; t += 256){
            int rr = t >> 4, kk = t & 15;
            int j = j0 + rr;
            xs1[kk][rr] = (j < 384) ? w_ih[(size_t)j*256 + kc + kk]       : 0.f;
            xs2[kk][rr] = (j < 384) ? w_ih[(size_t)j*256 + 128 + kc + kk] : 0.f;
        }
        for (int t = tid; t < 1024; t += 256){
            int jj = t >> 4, kk = t & 15;
            ws1[kk][jj] = W_ein [(size_t)(kc+kk)*H_ + h0 + jj];
            ws2[kk][jj] = W_eout[(size_t)(kc+kk)*H_ + h0 + jj];
        }
        __syncthreads();
        #pragma unroll
        for (int kk = 0; kk < 16; kk++){
            float x1[4], x2[4], w1[4], w2[4];
            #pragma unroll
            for (int i=0;i<4;i++){ x1[i]=xs1[kk][(tr<<2)+i]; x2[i]=xs2[kk][(tr<<2)+i]; }
            #pragma unroll
            for (int j=0;j<4;j++){ w1[j]=ws1[kk][(tc<<2)+j]; w2[j]=ws2[kk][(tc<<2)+j]; }
            #pragma unroll
            for (int i=0;i<4;i++)
                #pragma unroll
                for (int j=0;j<4;j++){
                    acc1[i][j] = fmaf(x1[i], w1[j], acc1[i][j]);
                    acc2[i][j] = fmaf(x2[i], w2[j], acc2[i][j]);
                }
        }
        __syncthreads();
    }
    #pragma unroll
    for (int i=0;i<4;i++){
        int j = j0 + (tr<<2) + i;
        if (j >= 384) continue;
        #pragma unroll
        for (int q=0;q<4;q++){
            int h = h0 + (tc<<2) + q;
            g_Wcat[(size_t)j*KX + h]       = acc1[i][q];
            g_Wcat[(size_t)j*KX + 128 + h] = acc2[i][q];
        }
    }
}

// ---------------- prep B: Wcat cols [256:384) = w_hh, cols 384/385 = uin/uout, bias bc ----------------
__global__ void k_prep_wcat2(const float* __restrict__ w_ih, const float* __restrict__ w_hh,
                             const float* __restrict__ b_ih, const float* __restrict__ b_hh,
                             const float* __restrict__ b_ein, const float* __restrict__ b_eout,
                             const float* __restrict__ b_iah, const float* __restrict__ b_oah){
    int j = blockIdx.x, h = threadIdx.x;
    int jrow = (j < 384) ? j : 256 + (j - 384);
    g_Wcat[(size_t)j*KX + 256 + h] = w_hh[(size_t)jrow*H_ + h];
    __shared__ float4 red[128];
    float4 v = make_float4(0.f,0.f,0.f,0.f);
    if (j < 384){
        float p1 = w_ih[(size_t)j*256 + h];
        float p2 = w_ih[(size_t)j*256 + 128 + h];
        v = make_float4(p1*b_ein[h], p2*b_eout[h], p1*b_iah[h], p2*b_oah[h]);
    }
    red[h] = v;
    for (int s = 64; s; s >>= 1){
        __syncthreads();
        if (h < s){
            float4 o = red[h+s];
            red[h].x += o.x; red[h].y += o.y; red[h].z += o.z; red[h].w += o.w;
        }
    }
    __syncthreads();
    if (h == 0){
        float4 t = red[0];
        g_Wcat[(size_t)j*KX + 384] = (j < 384) ? t.x : 0.f;
        g_Wcat[(size_t)j*KX + 385] = (j < 384) ? t.y : 0.f;
        g_bc[j] = (j < 384) ? (b_ih[j] + b_hh[j] + t.z + t.w) : b_hh[jrow];
    }
    if (h < 14) g_Wcat[(size_t)j*KX + 386 + h] = 0.f;
}

// ---------------- gather + rowsums + Xcat init ----------------
__global__ void k_gather(const int* __restrict__ items, const float* __restrict__ emb,
                         const float* __restrict__ A){
    int r = blockIdx.x, tid = threadIdx.x;
    float v = emb[(size_t)items[r]*H_ + tid];
    g_hidden[r*H_ + tid] = v;
    g_Xcat[(size_t)r*KX + 256 + tid] = v;
    int lane = tid & 31, wid = tid >> 5;
    if (wid < 2){
        float s = 0.f;
        for (int m = lane; m < N_; m += 32) s += A[(size_t)r*2*N_ + wid*N_ + m];
        for (int d = 16; d; d >>= 1) s += __shfl_xor_sync(0xffffffffu, s, d);
        if (lane == 0) g_Xcat[(size_t)r*KX + 384 + wid] = s;
    }
    if (tid >= 64 && tid < 78) g_Xcat[(size_t)r*KX + 386 + (tid - 64)] = 0.f;
}

// ---------------- prop2: AHin/AHout = A @ hidden -> Xcat[:,0:256) ----------------
__global__ void k_prop2(const float* __restrict__ A){
    int r = blockIdx.x;
    int b = r / N_;
    int h = threadIdx.x;
    __shared__ float arow[2*N_];
    if (h < 2*N_) arow[h] = A[(size_t)r*2*N_ + h];
    __syncthreads();
    float sin = 0.f, sout = 0.f;
    #pragma unroll 10
    for (int m = 0; m < N_; m++){
        sin  = fmaf(arow[m],     g_hidden[(b*N_+m)*H_ + h], sin);
        sout = fmaf(arow[N_+m],  g_hidden[(b*N_+m)*H_ + h], sout);
    }
    g_Xcat[(size_t)r*KX + h]       = sin;
    g_Xcat[(size_t)r*KX + 128 + h] = sout;
}

// ---------------- GRU gate from T; updates hidden + Xcat hidden slot ----------------
__global__ void k_gate2(){
    int r = blockIdx.x, h = threadIdx.x;
    float sr  = g_T[(size_t)r*512 + h];
    float si  = g_T[(size_t)r*512 + 128 + h];
    float sn  = g_T[(size_t)r*512 + 256 + h];
    float hnv = g_T[(size_t)r*512 + 384 + h];
    float rg = sigmoidf_(sr);
    float ig = sigmoidf_(si);
    float ng = tanhf(sn - hnv + rg * hnv);
    float hv = g_hidden[(size_t)r*H_ + h];
    float nh = ng + ig * (hv - ng);
    g_hidden[(size_t)r*H_ + h] = nh;
    g_Xcat[(size_t)r*KX + 256 + h] = nh;
}

// ---------------- fused attention head: len, ht, q1, alpha, cat, a ----------------
__global__ void k_alpha2(const int* __restrict__ mask, const float* __restrict__ w3,
                         const float* __restrict__ W_one, const float* __restrict__ b_one,
                         const float* __restrict__ W_tr,  const float* __restrict__ b_tr){
    int b = blockIdx.x, tid = threadIdx.x;
    __shared__ int slen;
    __shared__ float hts[128], q1s[128], logits[N_], cats[256];
    int warp = tid >> 5, lane = tid & 31;
    if (tid == 0){
        int s = 0;
        for (int n = 0; n < N_; n++) s += mask[b*N_+n];
        slen = s;
        g_len[b] = s;
    }
    __syncthreads();
    const int len = slen;
    float htv = g_hidden[(size_t)(b*N_ + len - 1)*H_ + tid];
    hts[tid] = htv;
    __syncthreads();
    float q1 = b_one[tid];
    #pragma unroll 8
    for (int k = 0; k < H_; k++) q1 = fmaf(hts[k], W_one[(size_t)tid*H_ + k], q1);
    q1s[tid] = q1;
    __syncthreads();
    for (int n = warp; n < len; n += 4){
        float s = 0.f;
        for (int hh = lane; hh < H_; hh += 32){
            float x = q1s[hh] + g_q2qt[(size_t)(b*N_+n)*256 + hh];
            s += sigmoidf_(x) * w3[hh];
        }
        for (int d = 16; d; d >>= 1) s += __shfl_xor_sync(0xffffffffu, s, d);
        if (lane == 0) logits[n] = s;
    }
    __syncthreads();
    float mx = -3.0e38f;
    for (int n = 0; n < len; n++) mx = fmaxf(mx, logits[n]);
    float denom = 0.f;
    for (int n = 0; n < len; n++) denom += expf(logits[n]-mx);
    float s = 0.f;
    for (int n = 0; n < len; n++)
        s = fmaf(expf(logits[n]-mx), g_hidden[(size_t)(b*N_+n)*H_ + tid], s);
    cats[tid] = s / denom;
    cats[128 + tid] = htv;
    __syncthreads();
    float av = b_tr[tid];
    #pragma unroll 8
    for (int k = 0; k < 256; k++) av = fmaf(cats[k], W_tr[(size_t)tid*256 + k], av);
    g_a[b*H_ + tid] = av;
}

// ---------------- prep: emb -> bf16 hi/lo tiles, coalesced (warp = chunks x rows) ----------------
__global__ void k_prep_emb(const float* __restrict__ emb){
    int t = blockIdx.x;
    int c  = threadIdx.x & 15;       // chunk 0..15
    int r8 = threadIdx.x >> 4;       // 0..15
    uint4* dh = reinterpret_cast<uint4*>(g_embh);
    uint4* dl = reinterpret_cast<uint4*>(g_embl);
    #pragma unroll
    for (int it = 0; it < 8; it++){
        int r = r8 + (it << 4);      // 0..127
        int vg = t*128 + r;
        bool ok = vg < VM1;
        const float4* src = reinterpret_cast<const float4*>(emb + (size_t)(vg+1)*H_);
        float4 f0 = ok ? src[2*c]   : make_float4(0.f,0.f,0.f,0.f);
        float4 f1 = ok ? src[2*c+1] : make_float4(0.f,0.f,0.f,0.f);
        uint4 hi, lo;
        hi.x = bf16pair(f0.x, f0.y); hi.y = bf16pair(f0.z, f0.w);
        hi.z = bf16pair(f1.x, f1.y); hi.w = bf16pair(f1.z, f1.w);
        lo.x = bf16pair(f0.x - bf16of(f0.x), f0.y - bf16of(f0.y));
        lo.y = bf16pair(f0.z - bf16of(f0.z), f0.w - bf16of(f0.w));
        lo.z = bf16pair(f1.x - bf16of(f1.x), f1.y - bf16of(f1.y));
        lo.w = bf16pair(f1.z - bf16of(f1.z), f1.w - bf16of(f1.w));
        size_t o = ((size_t)t*128 + r)*16 + (c ^ (r & 7));
        dh[o] = hi;
        dl[o] = lo;
    }
}

// ---------------- pack qt/a -> per-batch B tiles; a at column len ----------------
__global__ void k_pack_tc(const float* __restrict__ a){
    int b = blockIdx.x, n = threadIdx.x;   // 64 threads
    int len = g_len[b];
    const float* src = (n < len) ? (g_q2qt + (size_t)(b*N_+n)*256 + 128)
                 : (n == len)    ? (a + (size_t)b*H_) : nullptr;
    uint4* dh = reinterpret_cast<uint4*>(g_qbh);
    uint4* dl = reinterpret_cast<uint4*>(g_qbl);
    size_t rb = ((size_t)b*64 + n)*16;
    #pragma unroll
    for (int c = 0; c < 16; c++){
        float4 f0 = src ? *reinterpret_cast<const float4*>(src + c*8)     : make_float4(0.f,0.f,0.f,0.f);
        float4 f1 = src ? *reinterpret_cast<const float4*>(src + c*8 + 4) : make_float4(0.f,0.f,0.f,0.f);
        uint4 hi, lo;
        hi.x = bf16pair(f0.x, f0.y); hi.y = bf16pair(f0.z, f0.w);
        hi.z = bf16pair(f1.x, f1.y); hi.w = bf16pair(f1.z, f1.w);
        lo.x = bf16pair(f0.x - bf16of(f0.x), f0.y - bf16of(f0.y));
        lo.y = bf16pair(f0.z - bf16of(f0.z), f0.w - bf16of(f0.w));
        lo.z = bf16pair(f1.x - bf16of(f1.x), f1.y - bf16of(f1.y));
        lo.w = bf16pair(f1.z - bf16of(f1.z), f1.w - bf16of(f1.w));
        size_t o = rb + (c ^ (n & 7));
        dh[o] = hi;
        dl[o] = lo;
    }
}

// ---------------- HMMA vocab scoring (len-bounded tiles, a-dot at column len) ----------------
#define SC_AH 0
#define SC_AL 32768
#define SC_BH 65536
#define SC_BL 81920
#define SC_BYTES 98304

__global__ void __launch_bounds__(256, 2)
k_scores_mma(float* __restrict__ out){
    extern __shared__ char sm[];
    unsigned sbase = smem_u32(sm);
    const int tid = threadIdx.x, wid = tid >> 5, lane = tid & 31;
    const int t = blockIdx.x;

    {
        const uint4* sh = reinterpret_cast<const uint4*>(g_embh + (size_t)t*32768);
        const uint4* sl = reinterpret_cast<const uint4*>(g_embl + (size_t)t*32768);
        uint4* dh = reinterpret_cast<uint4*>(sm + SC_AH);
        uint4* dl = reinterpret_cast<uint4*>(sm + SC_AL);
        #pragma unroll
        for (int i = 0; i < 8; i++){
            dh[tid + (i<<8)] = sh[tid + (i<<8)];
            dl[tid + (i<<8)] = sl[tid + (i<<8)];
        }
    }
    // initial B stage (batch 0)
    {
        const uint4* sh = reinterpret_cast<const uint4*>(g_qbh);
        const uint4* sl = reinterpret_cast<const uint4*>(g_qbl);
        uint4* dh = reinterpret_cast<uint4*>(sm + SC_BH);
        uint4* dl = reinterpret_cast<uint4*>(sm + SC_BL);
        #pragma unroll
        for (int i = 0; i < 4; i++){
            dh[tid + (i<<8)] = sh[tid + (i<<8)];
            dl[tid + (i<<8)] = sl[tid + (i<<8)];
        }
    }

    const int r0   = wid << 4;
    const int rowA = r0 + (lane & 15);
    const int phA  = rowA & 7;
    const int hl   = lane >> 4;
    const unsigned baseAh = sbase + SC_AH + rowA*256;
    const unsigned baseAl = sbase + SC_AL + rowA*256;
    const int rowB = (lane & 15);
    const int phB0 = rowB & 7;

    for (int b = 0; b < B_; b++){
        __syncthreads();
        // prefetch next batch's B into registers (hide latency under compute)
        uint4 pbh[4], pbl[4];
        if (b + 1 < B_){
            const uint4* sh = reinterpret_cast<const uint4*>(g_qbh + (size_t)(b+1)*16384);
            const uint4* sl = reinterpret_cast<const uint4*>(g_qbl + (size_t)(b+1)*16384);
            #pragma unroll
            for (int i = 0; i < 4; i++){
                pbh[i] = sh[tid + (i<<8)];
                pbl[i] = sl[tid + (i<<8)];
            }
        }
        const int len = g_len[b];

        float acc[8][4];
        #pragma unroll
        for (int ni = 0; ni < 8; ni++)
            #pragma unroll
            for (int e = 0; e < 4; e++) acc[ni][e] = 0.f;

        #pragma unroll
        for (int ks = 0; ks < 8; ks++){
            unsigned ah[4], al[4];
            unsigned offA = (unsigned)(((ks*2 + hl) ^ phA) << 4);
            ldsm4(ah[0], ah[1], ah[2], ah[3], baseAh + offA);
            ldsm4(al[0], al[1], al[2], al[3], baseAl + offA);
            unsigned bh[8][2], bl[8][2];
            #pragma unroll
            for (int ni2 = 0; ni2 < 4; ni2++){
                if (ni2*16 <= len){
                    unsigned offB = (unsigned)((ni2*16 + rowB)*256 + (((ks*2 + hl) ^ phB0) << 4));
                    unsigned q0,q1,q2,q3;
                    ldsm4(q0,q1,q2,q3, sbase + SC_BH + offB);
                    bh[2*ni2][0]=q0; bh[2*ni2][1]=q2; bh[2*ni2+1][0]=q1; bh[2*ni2+1][1]=q3;
                    ldsm4(q0,q1,q2,q3, sbase + SC_BL + offB);
                    bl[2*ni2][0]=q0; bl[2*ni2][1]=q2; bl[2*ni2+1][0]=q1; bl[2*ni2+1][1]=q3;
                }
            }
            #pragma unroll
            for (int ni = 0; ni < 8; ni++){
                if (ni*8 <= len){
                    mma16816(acc[ni], ah[0],ah[1],ah[2],ah[3], bh[ni][0], bh[ni][1]);
                    mma16816(acc[ni], ah[0],ah[1],ah[2],ah[3], bl[ni][0], bl[ni][1]);
                    mma16816(acc[ni], al[0],al[1],al[2],al[3], bh[ni][0], bh[ni][1]);
                }
            }
        }

        float av0 = 0.f, av8 = 0.f;
        #pragma unroll
        for (int ni = 0; ni < 8; ni++){
            if (ni == (len >> 3)){
                av0 = (len & 1) ? acc[ni][1] : acc[ni][0];
                av8 = (len & 1) ? acc[ni][3] : acc[ni][2];
            }
        }
        const int alane = (lane & ~3) | ((len & 7) >> 1);
        float ad0 = __shfl_sync(0xffffffffu, av0, alane);
        float ad8 = __shfl_sync(0xffffffffu, av8, alane);

        const int cb = (lane & 3) << 1;
        #pragma unroll
        for (int rh = 0; rh < 2; rh++){
            float mx = -3.0e38f;
            #pragma unroll
            for (int ni = 0; ni < 8; ni++){
                if (ni*8 < len){
                    #pragma unroll
                    for (int e = 0; e < 2; e++){
                        int n = ni*8 + cb + e;
                        if (n < len) mx = fmaxf(mx, acc[ni][rh*2+e]);
                    }
                }
            }
            mx = fmaxf(mx, __shfl_xor_sync(0xffffffffu, mx, 1));
            mx = fmaxf(mx, __shfl_xor_sync(0xffffffffu, mx, 2));
            float se = 0.f, sw = 0.f;
            #pragma unroll
            for (int ni = 0; ni < 8; ni++){
                if (ni*8 < len){
                    #pragma unroll
                    for (int e = 0; e < 2; e++){
                        int n = ni*8 + cb + e;
                        if (n < len){
                            float f = acc[ni][rh*2+e];
                            float ex = __expf(f - mx);
                            se += ex;
                            sw = fmaf(ex, f, sw);
                        }
                    }
                }
            }
            se += __shfl_xor_sync(0xffffffffu, se, 1);
            sw += __shfl_xor_sync(0xffffffffu, sw, 1);
            se += __shfl_xor_sync(0xffffffffu, se, 2);
            sw += __shfl_xor_sync(0xffffffffu, sw, 2);
            if ((lane & 3) == 0){
                int v = t*128 + r0 + (lane >> 2) + rh*8;
                if (v < VM1) out[(size_t)b*VM1 + v] = sw/se + (rh ? ad8 : ad0);
            }
        }

        __syncthreads();
        if (b + 1 < B_){
            uint4* dh = reinterpret_cast<uint4*>(sm + SC_BH);
            uint4* dl = reinterpret_cast<uint4*>(sm + SC_BL);
            #pragma unroll
            for (int i = 0; i < 4; i++){
                dh[tid + (i<<8)] = pbh[i];
                dl[tid + (i<<8)] = pbl[i];
            }
        }
    }
}

// ---------------- host side ----------------
static float* symaddr(const void* sym){
    void* p = nullptr;
    cudaGetSymbolAddress(&p, sym);
    return (float*)p;
}

extern "C" void kernel_launch(void* const* d_in, const int* in_sizes, int n_in,
                              void* d_out, int out_size){
    (void)in_sizes; (void)n_in; (void)out_size;
    const int*   items  = (const int*)  d_in[0];
    const float* A      = (const float*)d_in[1];
    const int*   mask   = (const int*)  d_in[2];
    const float* emb    = (const float*)d_in[3];
    const float* w_ih   = (const float*)d_in[4];
    const float* w_hh   = (const float*)d_in[5];
    const float* b_ih   = (const float*)d_in[6];
    const float* b_hh   = (const float*)d_in[7];
    const float* b_iah  = (const float*)d_in[8];
    const float* b_oah  = (const float*)d_in[9];
    const float* W_ein  = (const float*)d_in[10];
    const float* b_ein  = (const float*)d_in[11];
    const float* W_eout = (const float*)d_in[12];
    const float* b_eout = (const float*)d_in[13];
    const float* W_one  = (const float*)d_in[14];
    const float* b_one  = (const float*)d_in[15];
    const float* W_two  = (const float*)d_in[16];
    const float* b_two  = (const float*)d_in[17];
    const float* w_three= (const float*)d_in[18];
    const float* W_tr   = (const float*)d_in[19];
    const float* b_tr   = (const float*)d_in[20];
    const float* W_t    = (const float*)d_in[21];
    float* out = (float*)d_out;

    float* Xcat = symaddr(g_Xcat);
    float* Wcat = symaddr(g_Wcat);
    float* bc   = symaddr(g_bc);
    float* T    = symaddr(g_T);
    float* hid  = symaddr(g_hidden);
    float* q2qt = symaddr(g_q2qt);
    float* a    = symaddr(g_a);

    static cudaStream_t s2 = nullptr;
    static cudaEvent_t evRoot = nullptr, evW = nullptr, evE = nullptr;
    static int init_done = 0;
    if (!init_done){
        cudaFuncSetAttribute(k_scores_mma, cudaFuncAttributeMaxDynamicSharedMemorySize, SC_BYTES);
        cudaStreamCreateWithFlags(&s2, cudaStreamNonBlocking);
        cudaEventCreateWithFlags(&evRoot, cudaEventDisableTiming);
        cudaEventCreateWithFlags(&evW,    cudaEventDisableTiming);
        cudaEventCreateWithFlags(&evE,    cudaEventDisableTiming);
        init_done = 1;
    }

    // fork: weight-fold + emb prep on s2, overlapped with gather/GNN on main stream
    cudaEventRecord(evRoot, 0);
    cudaStreamWaitEvent(s2, evRoot, 0);
    {
        dim3 g(2, 6);
        k_prep_wa<<<g, 256, 0, s2>>>(w_ih, W_ein, W_eout);
    }
    k_prep_wcat2<<<512, 128, 0, s2>>>(w_ih, w_hh, b_ih, b_hh, b_ein, b_eout, b_iah, b_oah);
    cudaEventRecord(evW, s2);
    k_prep_emb<<<NT_, 256, 0, s2>>>(emb);
    cudaEventRecord(evE, s2);

    // main chain
    k_gather<<<R_, H_>>>(items, emb, A);
    k_prop2<<<R_, H_>>>(A);
    cudaStreamWaitEvent(0, evW, 0);     // join Wcat before first GNN GEMM
    for (int step = 0; step < 2; step++){
        if (step) k_prop2<<<R_, H_>>>(A);
        dim3 gt(8, 7);
        k_gemm_f<<<gt, 256>>>(Xcat, Wcat, Wcat, 512, bc, nullptr, T, R_, KX, 512);
        k_gate2<<<R_, H_>>>();
    }

    // attention head: one GEMM produces [q2 | qt]
    {
        dim3 gq(4, 7);
        k_gemm_f<<<gq, 256>>>(hid, W_two, W_t, 128, b_two, nullptr, q2qt, R_, H_, 256);
    }
    k_alpha2<<<B_, H_>>>(mask, w_three, W_one, b_one, W_tr, b_tr);
    k_pack_tc<<<B_, 64>>>(a);

    cudaStreamWaitEvent(0, evE, 0);     // join emb tiles before scoring
    k_scores_mma<<<NT_, 256, SC_BYTES>>>(out);
}

// round 13
// speedup vs baseline: 1.1726x; 1.1726x over previous
#include <cuda_runtime.h>
#include <cuda_bf16.h>
#include <math.h>

// Problem constants
#define B_  16
#define N_  50
#define H_  128
#define V_  40000
#define VM1 39999      // V-1 rows of b_emb / output columns
#define R_  (B_*N_)    // 800 rows
#define NT_ 313        // ceil(VM1/128) vocab tiles (128 rows each)
#define KX  400        // padded Xcat/Wcat K (386 used)

// ---------------- scratch (static __device__, no allocs) ----------------
__device__ float g_hidden[R_*H_];
__device__ float g_Xcat  [R_*KX];      // [AHin(128) | AHout(128) | hidden(128) | rsin | rsout | pad]
__device__ float g_Wcat  [512*KX];
__device__ float g_bc    [512];
__device__ float g_T     [R_*512];
__device__ float g_q2qt  [R_*256];     // cols 0..127 = q2, cols 128..255 = qt
__device__ float g_a     [B_*H_];
// HMMA staging: bf16 hi/lo split, ldmatrix XOR-chunk swizzled layouts
__device__ unsigned char g_embh[(size_t)NT_*32768];
__device__ unsigned char g_embl[(size_t)NT_*32768];
__device__ unsigned char g_qbh [B_*16384];
__device__ unsigned char g_qbl [B_*16384];
__device__ int g_len[B_];

// ---------------- small helpers ----------------
__device__ __forceinline__ float sigmoidf_(float x){ return 1.f/(1.f+expf(-x)); }

__device__ __forceinline__ unsigned smem_u32(const void* p){
    unsigned a;
    asm("{ .reg .u64 t; cvta.to.shared.u64 t, %1; cvt.u32.u64 %0, t; }" : "=r"(a) : "l"(p));
    return a;
}
__device__ __forceinline__ unsigned long long pack2(float x, float y){
    unsigned long long r;
    asm("mov.b64 %0, {%1, %2};" : "=l"(r) : "f"(x), "f"(y));
    return r;
}
__device__ __forceinline__ unsigned long long fma2(unsigned long long a,
                                                   unsigned long long b,
                                                   unsigned long long c){
    unsigned long long d;
    asm("fma.rn.f32x2 %0, %1, %2, %3;" : "=l"(d) : "l"(a), "l"(b), "l"(c));
    return d;
}
__device__ __forceinline__ float lo2(unsigned long long u){
    return __uint_as_float((unsigned)(u & 0xffffffffULL));
}
__device__ __forceinline__ float hi2(unsigned long long u){
    return __uint_as_float((unsigned)(u >> 32));
}
__device__ __forceinline__ unsigned bf16pair(float a, float b){
    __nv_bfloat162 t = __floats2bfloat162_rn(a, b);
    return *reinterpret_cast<unsigned*>(&t);
}
__device__ __forceinline__ float bf16of(float x){
    return __bfloat162float(__float2bfloat16(x));
}
__device__ __forceinline__ void ldsm4(unsigned& r0, unsigned& r1, unsigned& r2, unsigned& r3,
                                      unsigned addr){
    asm volatile("ldmatrix.sync.aligned.m8n8.x4.shared.b16 {%0,%1,%2,%3}, [%4];"
                 : "=r"(r0),"=r"(r1),"=r"(r2),"=r"(r3) : "r"(addr));
}
__device__ __forceinline__ void mma16816(float* c, unsigned a0, unsigned a1, unsigned a2,
                                         unsigned a3, unsigned b0, unsigned b1){
    asm volatile(
        "mma.sync.aligned.m16n8k16.row.col.f32.bf16.bf16.f32 "
        "{%0,%1,%2,%3}, {%4,%5,%6,%7}, {%8,%9}, {%0,%1,%2,%3};"
        : "+f"(c[0]), "+f"(c[1]), "+f"(c[2]), "+f"(c[3])
        : "r"(a0), "r"(a1), "r"(a2), "r"(a3), "r"(b0), "r"(b1));
}

// ---------------- fast SGEMM: 128x64 tile, 256 threads, 8r x 4j per thread ----------------
// out[r,j] = sum_k X[r,k]*W[j,k] (+bias). W row j from W0 (j<Jsplit) or W1. K%16==0.
__global__ void __launch_bounds__(256)
k_gemm_f(const float* __restrict__ X, const float* __restrict__ W0,
         const float* __restrict__ W1, int Jsplit,
         const float* __restrict__ bias0, const float* __restrict__ bias1,
         float* __restrict__ out, int R, int K, int J){
    __shared__ __align__(16) float xs[16][132];
    __shared__ __align__(16) float ws[16][68];
    const int tid = threadIdx.x;
    const int tr = tid >> 4, tc = tid & 15;
    const int r0 = blockIdx.y << 7, j0 = blockIdx.x << 6;
    unsigned long long acc[4][4];
    #pragma unroll
    for (int p=0;p<4;p++)
        #pragma unroll
        for (int j=0;j<4;j++) acc[p][j] = 0ULL;

    for (int kc = 0; kc < K; kc += 16){
        // stage X chunk: 128 rows x 16 k (512 float4 loads)
        #pragma unroll
        for (int it = 0; it < 2; it++){
            int idx = tid + (it<<8);
            int rr = idx >> 2, kq = idx & 3;
            float4 v = make_float4(0.f,0.f,0.f,0.f);
            if (r0 + rr < R)
                v = *reinterpret_cast<const float4*>(X + (size_t)(r0+rr)*K + kc + (kq<<2));
            xs[(kq<<2)+0][rr] = v.x;
            xs[(kq<<2)+1][rr] = v.y;
            xs[(kq<<2)+2][rr] = v.z;
            xs[(kq<<2)+3][rr] = v.w;
        }
        // stage W chunk: 64 j x 16 k (256 float4 loads)
        {
            int jj = tid >> 2, kq = tid & 3;
            int j = j0 + jj;
            float4 v = make_float4(0.f,0.f,0.f,0.f);
            if (j < J){
                const float* Wr = (j < Jsplit) ? (W0 + (size_t)j*K)
                                               : (W1 + (size_t)(j-Jsplit)*K);
                v = *reinterpret_cast<const float4*>(Wr + kc + (kq<<2));
            }
            ws[(kq<<2)+0][jj] = v.x;
            ws[(kq<<2)+1][jj] = v.y;
            ws[(kq<<2)+2][jj] = v.z;
            ws[(kq<<2)+3][jj] = v.w;
        }
        __syncthreads();
        #pragma unroll
        for (int kk = 0; kk < 16; kk++){
            float4 xA = *reinterpret_cast<const float4*>(&xs[kk][tr<<3]);
            float4 xB = *reinterpret_cast<const float4*>(&xs[kk][(tr<<3)+4]);
            float4 wv = *reinterpret_cast<const float4*>(&ws[kk][tc<<2]);
            unsigned long long xu0 = pack2(xA.x, xA.y);
            unsigned long long xu1 = pack2(xA.z, xA.w);
            unsigned long long xu2 = pack2(xB.x, xB.y);
            unsigned long long xu3 = pack2(xB.z, xB.w);
            float wf[4] = {wv.x, wv.y, wv.z, wv.w};
            #pragma unroll
            for (int j = 0; j < 4; j++){
                unsigned long long wb = pack2(wf[j], wf[j]);
                acc[0][j] = fma2(xu0, wb, acc[0][j]);
                acc[1][j] = fma2(xu1, wb, acc[1][j]);
                acc[2][j] = fma2(xu2, wb, acc[2][j]);
                acc[3][j] = fma2(xu3, wb, acc[3][j]);
            }
        }
        __syncthreads();
    }
    #pragma unroll
    for (int p = 0; p < 4; p++){
        #pragma unroll
        for (int e = 0; e < 2; e++){
            int r = r0 + (tr<<3) + (p<<1) + e;
            if (r >= R) continue;
            #pragma unroll
            for (int j = 0; j < 4; j++){
                int jj = j0 + (tc<<2) + j;
                if (jj >= J) continue;
                float bv = (jj < Jsplit) ? (bias0 ? bias0[jj] : 0.f)
                                         : (bias1 ? bias1[jj - Jsplit] : 0.f);
                float val = e ? hi2(acc[p][j]) : lo2(acc[p][j]);
                out[(size_t)r*J + jj] = val + bv;
            }
        }
    }
}

// ---------------- prep A: WA/WB = w_ih halves @ W_ein/W_eout -> Wcat cols [0:256) ----------------
__global__ void k_prep_wa(const float* __restrict__ w_ih, const float* __restrict__ W_ein,
                          const float* __restrict__ W_eout){
    __shared__ float xs1[16][65], xs2[16][65];
    __shared__ float ws1[16][65], ws2[16][65];
    int tid = threadIdx.x;
    int tr = tid >> 4, tc = tid & 15;
    int j0 = blockIdx.y << 6, h0 = blockIdx.x << 6;
    float acc1[4][4] = {}, acc2[4][4] = {};
    for (int kc = 0; kc < H_; kc += 16){
        for (int t = tid; t < 1024; t += 256){
            int rr = t >> 4, kk = t & 15;
            int j = j0 + rr;
            xs1[kk][rr] = (j < 384) ? w_ih[(size_t)j*256 + kc + kk]       : 0.f;
            xs2[kk][rr] = (j < 384) ? w_ih[(size_t)j*256 + 128 + kc + kk] : 0.f;
        }
        for (int t = tid; t < 1024; t += 256){
            int jj = t >> 4, kk = t & 15;
            ws1[kk][jj] = W_ein [(size_t)(kc+kk)*H_ + h0 + jj];
            ws2[kk][jj] = W_eout[(size_t)(kc+kk)*H_ + h0 + jj];
        }
        __syncthreads();
        #pragma unroll
        for (int kk = 0; kk < 16; kk++){
            float x1[4], x2[4], w1[4], w2[4];
            #pragma unroll
            for (int i=0;i<4;i++){ x1[i]=xs1[kk][(tr<<2)+i]; x2[i]=xs2[kk][(tr<<2)+i]; }
            #pragma unroll
            for (int j=0;j<4;j++){ w1[j]=ws1[kk][(tc<<2)+j]; w2[j]=ws2[kk][(tc<<2)+j]; }
            #pragma unroll
            for (int i=0;i<4;i++)
                #pragma unroll
                for (int j=0;j<4;j++){
                    acc1[i][j] = fmaf(x1[i], w1[j], acc1[i][j]);
                    acc2[i][j] = fmaf(x2[i], w2[j], acc2[i][j]);
                }
        }
        __syncthreads();
    }
    #pragma unroll
    for (int i=0;i<4;i++){
        int j = j0 + (tr<<2) + i;
        if (j >= 384) continue;
        #pragma unroll
        for (int q=0;q<4;q++){
            int h = h0 + (tc<<2) + q;
            g_Wcat[(size_t)j*KX + h]       = acc1[i][q];
            g_Wcat[(size_t)j*KX + 128 + h] = acc2[i][q];
        }
    }
}

// ---------------- prep B: Wcat cols [256:384) = w_hh, cols 384/385 = uin/uout, bias bc ----------------
__global__ void k_prep_wcat2(const float* __restrict__ w_ih, const float* __restrict__ w_hh,
                             const float* __restrict__ b_ih, const float* __restrict__ b_hh,
                             const float* __restrict__ b_ein, const float* __restrict__ b_eout,
                             const float* __restrict__ b_iah, const float* __restrict__ b_oah){
    int j = blockIdx.x, h = threadIdx.x;
    int jrow = (j < 384) ? j : 256 + (j - 384);
    g_Wcat[(size_t)j*KX + 256 + h] = w_hh[(size_t)jrow*H_ + h];
    __shared__ float4 red[128];
    float4 v = make_float4(0.f,0.f,0.f,0.f);
    if (j < 384){
        float p1 = w_ih[(size_t)j*256 + h];
        float p2 = w_ih[(size_t)j*256 + 128 + h];
        v = make_float4(p1*b_ein[h], p2*b_eout[h], p1*b_iah[h], p2*b_oah[h]);
    }
    red[h] = v;
    for (int s = 64; s; s >>= 1){
        __syncthreads();
        if (h < s){
            float4 o = red[h+s];
            red[h].x += o.x; red[h].y += o.y; red[h].z += o.z; red[h].w += o.w;
        }
    }
    __syncthreads();
    if (h == 0){
        float4 t = red[0];
        g_Wcat[(size_t)j*KX + 384] = (j < 384) ? t.x : 0.f;
        g_Wcat[(size_t)j*KX + 385] = (j < 384) ? t.y : 0.f;
        g_bc[j] = (j < 384) ? (b_ih[j] + b_hh[j] + t.z + t.w) : b_hh[jrow];
    }
    if (h < 14) g_Wcat[(size_t)j*KX + 386 + h] = 0.f;
}

// ---------------- gather + rowsums + Xcat init ----------------
__global__ void k_gather(const int* __restrict__ items, const float* __restrict__ emb,
                         const float* __restrict__ A){
    int r = blockIdx.x, tid = threadIdx.x;
    float v = emb[(size_t)items[r]*H_ + tid];
    g_hidden[r*H_ + tid] = v;
    g_Xcat[(size_t)r*KX + 256 + tid] = v;
    int lane = tid & 31, wid = tid >> 5;
    if (wid < 2){
        float s = 0.f;
        for (int m = lane; m < N_; m += 32) s += A[(size_t)r*2*N_ + wid*N_ + m];
        for (int d = 16; d; d >>= 1) s += __shfl_xor_sync(0xffffffffu, s, d);
        if (lane == 0) g_Xcat[(size_t)r*KX + 384 + wid] = s;
    }
    if (tid >= 64 && tid < 78) g_Xcat[(size_t)r*KX + 386 + (tid - 64)] = 0.f;
}

// ---------------- prop2: AHin/AHout = A @ hidden -> Xcat[:,0:256) ----------------
__global__ void k_prop2(const float* __restrict__ A){
    int r = blockIdx.x;
    int b = r / N_;
    int h = threadIdx.x;
    __shared__ float arow[2*N_];
    if (h < 2*N_) arow[h] = A[(size_t)r*2*N_ + h];
    __syncthreads();
    float sin = 0.f, sout = 0.f;
    #pragma unroll 10
    for (int m = 0; m < N_; m++){
        sin  = fmaf(arow[m],     g_hidden[(b*N_+m)*H_ + h], sin);
        sout = fmaf(arow[N_+m],  g_hidden[(b*N_+m)*H_ + h], sout);
    }
    g_Xcat[(size_t)r*KX + h]       = sin;
    g_Xcat[(size_t)r*KX + 128 + h] = sout;
}

// ---------------- GRU gate from T; updates hidden + Xcat hidden slot ----------------
__global__ void k_gate2(){
    int r = blockIdx.x, h = threadIdx.x;
    float sr  = g_T[(size_t)r*512 + h];
    float si  = g_T[(size_t)r*512 + 128 + h];
    float sn  = g_T[(size_t)r*512 + 256 + h];
    float hnv = g_T[(size_t)r*512 + 384 + h];
    float rg = sigmoidf_(sr);
    float ig = sigmoidf_(si);
    float ng = tanhf(sn - hnv + rg * hnv);
    float hv = g_hidden[(size_t)r*H_ + h];
    float nh = ng + ig * (hv - ng);
    g_hidden[(size_t)r*H_ + h] = nh;
    g_Xcat[(size_t)r*KX + 256 + h] = nh;
}

// ---------------- fused attention head: len, ht, q1, alpha, cat, a ----------------
__global__ void k_alpha2(const int* __restrict__ mask, const float* __restrict__ w3,
                         const float* __restrict__ W_one, const float* __restrict__ b_one,
                         const float* __restrict__ W_tr,  const float* __restrict__ b_tr){
    int b = blockIdx.x, tid = threadIdx.x;
    __shared__ int slen;
    __shared__ float hts[128], q1s[128], logits[N_], cats[256];
    int warp = tid >> 5, lane = tid & 31;
    if (tid == 0){
        int s = 0;
        for (int n = 0; n < N_; n++) s += mask[b*N_+n];
        slen = s;
        g_len[b] = s;
    }
    __syncthreads();
    const int len = slen;
    float htv = g_hidden[(size_t)(b*N_ + len - 1)*H_ + tid];
    hts[tid] = htv;
    __syncthreads();
    float q1 = b_one[tid];
    #pragma unroll 8
    for (int k = 0; k < H_; k++) q1 = fmaf(hts[k], W_one[(size_t)tid*H_ + k], q1);
    q1s[tid] = q1;
    __syncthreads();
    for (int n = warp; n < len; n += 4){
        float s = 0.f;
        for (int hh = lane; hh < H_; hh += 32){
            float x = q1s[hh] + g_q2qt[(size_t)(b*N_+n)*256 + hh];
            s += sigmoidf_(x) * w3[hh];
        }
        for (int d = 16; d; d >>= 1) s += __shfl_xor_sync(0xffffffffu, s, d);
        if (lane == 0) logits[n] = s;
    }
    __syncthreads();
    float mx = -3.0e38f;
    for (int n = 0; n < len; n++) mx = fmaxf(mx, logits[n]);
    float denom = 0.f;
    for (int n = 0; n < len; n++) denom += expf(logits[n]-mx);
    float s = 0.f;
    for (int n = 0; n < len; n++)
        s = fmaf(expf(logits[n]-mx), g_hidden[(size_t)(b*N_+n)*H_ + tid], s);
    cats[tid] = s / denom;
    cats[128 + tid] = htv;
    __syncthreads();
    float av = b_tr[tid];
    #pragma unroll 8
    for (int k = 0; k < 256; k++) av = fmaf(cats[k], W_tr[(size_t)tid*256 + k], av);
    g_a[b*H_ + tid] = av;
}

// ---------------- prep: emb -> bf16 hi/lo tiles, coalesced (warp = chunks x rows) ----------------
__global__ void k_prep_emb(const float* __restrict__ emb){
    int t = blockIdx.x;
    int c  = threadIdx.x & 15;       // chunk 0..15
    int r8 = threadIdx.x >> 4;       // 0..15
    uint4* dh = reinterpret_cast<uint4*>(g_embh);
    uint4* dl = reinterpret_cast<uint4*>(g_embl);
    #pragma unroll
    for (int it = 0; it < 8; it++){
        int r = r8 + (it << 4);      // 0..127
        int vg = t*128 + r;
        bool ok = vg < VM1;
        const float4* src = reinterpret_cast<const float4*>(emb + (size_t)(vg+1)*H_);
        float4 f0 = ok ? src[2*c]   : make_float4(0.f,0.f,0.f,0.f);
        float4 f1 = ok ? src[2*c+1] : make_float4(0.f,0.f,0.f,0.f);
        uint4 hi, lo;
        hi.x = bf16pair(f0.x, f0.y); hi.y = bf16pair(f0.z, f0.w);
        hi.z = bf16pair(f1.x, f1.y); hi.w = bf16pair(f1.z, f1.w);
        lo.x = bf16pair(f0.x - bf16of(f0.x), f0.y - bf16of(f0.y));
        lo.y = bf16pair(f0.z - bf16of(f0.z), f0.w - bf16of(f0.w));
        lo.z = bf16pair(f1.x - bf16of(f1.x), f1.y - bf16of(f1.y));
        lo.w = bf16pair(f1.z - bf16of(f1.z), f1.w - bf16of(f1.w));
        size_t o = ((size_t)t*128 + r)*16 + (c ^ (r & 7));
        dh[o] = hi;
        dl[o] = lo;
    }
}

// ---------------- pack qt/a -> per-batch B tiles; a at column len ----------------
__global__ void k_pack_tc(const float* __restrict__ a){
    int b = blockIdx.x, n = threadIdx.x;   // 64 threads
    int len = g_len[b];
    const float* src = (n < len) ? (g_q2qt + (size_t)(b*N_+n)*256 + 128)
                 : (n == len)    ? (a + (size_t)b*H_) : nullptr;
    uint4* dh = reinterpret_cast<uint4*>(g_qbh);
    uint4* dl = reinterpret_cast<uint4*>(g_qbl);
    size_t rb = ((size_t)b*64 + n)*16;
    #pragma unroll
    for (int c = 0; c < 16; c++){
        float4 f0 = src ? *reinterpret_cast<const float4*>(src + c*8)     : make_float4(0.f,0.f,0.f,0.f);
        float4 f1 = src ? *reinterpret_cast<const float4*>(src + c*8 + 4) : make_float4(0.f,0.f,0.f,0.f);
        uint4 hi, lo;
        hi.x = bf16pair(f0.x, f0.y); hi.y = bf16pair(f0.z, f0.w);
        hi.z = bf16pair(f1.x, f1.y); hi.w = bf16pair(f1.z, f1.w);
        lo.x = bf16pair(f0.x - bf16of(f0.x), f0.y - bf16of(f0.y));
        lo.y = bf16pair(f0.z - bf16of(f0.z), f0.w - bf16of(f0.w));
        lo.z = bf16pair(f1.x - bf16of(f1.x), f1.y - bf16of(f1.y));
        lo.w = bf16pair(f1.z - bf16of(f1.z), f1.w - bf16of(f1.w));
        size_t o = rb + (c ^ (n & 7));
        dh[o] = hi;
        dl[o] = lo;
    }
}

// ---------------- HMMA vocab scoring (len-bounded tiles, a-dot at column len) ----------------
#define SC_AH 0
#define SC_AL 32768
#define SC_BH 65536
#define SC_BL 81920
#define SC_BYTES 98304

__global__ void __launch_bounds__(256, 2)
k_scores_mma(float* __restrict__ out){
    extern __shared__ char sm[];
    unsigned sbase = smem_u32(sm);
    const int tid = threadIdx.x, wid = tid >> 5, lane = tid & 31;
    const int t = blockIdx.x;

    // stage A tiles (pre-swizzled): 32KB hi + 32KB lo
    {
        const uint4* sh = reinterpret_cast<const uint4*>(g_embh + (size_t)t*32768);
        const uint4* sl = reinterpret_cast<const uint4*>(g_embl + (size_t)t*32768);
        uint4* dh = reinterpret_cast<uint4*>(sm + SC_AH);
        uint4* dl = reinterpret_cast<uint4*>(sm + SC_AL);
        #pragma unroll
        for (int i = 0; i < 8; i++){
            dh[tid + (i<<8)] = sh[tid + (i<<8)];
            dl[tid + (i<<8)] = sl[tid + (i<<8)];
        }
    }

    const int r0   = wid << 4;
    const int rowA = r0 + (lane & 15);
    const int phA  = rowA & 7;
    const int hl   = lane >> 4;
    const unsigned baseAh = sbase + SC_AH + rowA*256;
    const unsigned baseAl = sbase + SC_AL + rowA*256;
    const int rowB = (lane & 15);
    const int phB0 = rowB & 7;

    for (int b = 0; b < B_; b++){
        __syncthreads();
        // stage B tiles (16KB hi + 16KB lo)
        {
            const uint4* sh = reinterpret_cast<const uint4*>(g_qbh + (size_t)b*16384);
            const uint4* sl = reinterpret_cast<const uint4*>(g_qbl + (size_t)b*16384);
            uint4* dh = reinterpret_cast<uint4*>(sm + SC_BH);
            uint4* dl = reinterpret_cast<uint4*>(sm + SC_BL);
            #pragma unroll
            for (int i = 0; i < 4; i++){
                dh[tid + (i<<8)] = sh[tid + (i<<8)];
                dl[tid + (i<<8)] = sl[tid + (i<<8)];
            }
        }
        __syncthreads();
        const int len = g_len[b];

        float acc[8][4];
        #pragma unroll
        for (int ni = 0; ni < 8; ni++)
            #pragma unroll
            for (int e = 0; e < 4; e++) acc[ni][e] = 0.f;

        #pragma unroll
        for (int ks = 0; ks < 8; ks++){
            unsigned ah[4], al[4];
            unsigned offA = (unsigned)(((ks*2 + hl) ^ phA) << 4);
            ldsm4(ah[0], ah[1], ah[2], ah[3], baseAh + offA);
            ldsm4(al[0], al[1], al[2], al[3], baseAl + offA);
            unsigned bh[8][2], bl[8][2];
            #pragma unroll
            for (int ni2 = 0; ni2 < 4; ni2++){
                if (ni2*16 <= len){
                    unsigned offB = (unsigned)((ni2*16 + rowB)*256 + (((ks*2 + hl) ^ phB0) << 4));
                    unsigned q0,q1,q2,q3;
                    ldsm4(q0,q1,q2,q3, sbase + SC_BH + offB);
                    bh[2*ni2][0]=q0; bh[2*ni2][1]=q2; bh[2*ni2+1][0]=q1; bh[2*ni2+1][1]=q3;
                    ldsm4(q0,q1,q2,q3, sbase + SC_BL + offB);
                    bl[2*ni2][0]=q0; bl[2*ni2][1]=q2; bl[2*ni2+1][0]=q1; bl[2*ni2+1][1]=q3;
                }
            }
            #pragma unroll
            for (int ni = 0; ni < 8; ni++){
                if (ni*8 <= len){
                    mma16816(acc[ni], ah[0],ah[1],ah[2],ah[3], bh[ni][0], bh[ni][1]);
                    mma16816(acc[ni], ah[0],ah[1],ah[2],ah[3], bl[ni][0], bl[ni][1]);
                    mma16816(acc[ni], al[0],al[1],al[2],al[3], bh[ni][0], bh[ni][1]);
                }
            }
        }

        // a-dot lives at column len: tile len>>3, in-tile col len&7
        float av0 = 0.f, av8 = 0.f;
        #pragma unroll
        for (int ni = 0; ni < 8; ni++){
            if (ni == (len >> 3)){
                av0 = (len & 1) ? acc[ni][1] : acc[ni][0];
                av8 = (len & 1) ? acc[ni][3] : acc[ni][2];
            }
        }
        const int alane = (lane & ~3) | ((len & 7) >> 1);
        float ad0 = __shfl_sync(0xffffffffu, av0, alane);
        float ad8 = __shfl_sync(0xffffffffu, av8, alane);

        const int cb = (lane & 3) << 1;
        #pragma unroll
        for (int rh = 0; rh < 2; rh++){
            float mx = -3.0e38f;
            #pragma unroll
            for (int ni = 0; ni < 8; ni++){
                if (ni*8 < len){
                    #pragma unroll
                    for (int e = 0; e < 2; e++){
                        int n = ni*8 + cb + e;
                        if (n < len) mx = fmaxf(mx, acc[ni][rh*2+e]);
                    }
                }
            }
            mx = fmaxf(mx, __shfl_xor_sync(0xffffffffu, mx, 1));
            mx = fmaxf(mx, __shfl_xor_sync(0xffffffffu, mx, 2));
            float se = 0.f, sw = 0.f;
            #pragma unroll
            for (int ni = 0; ni < 8; ni++){
                if (ni*8 < len){
                    #pragma unroll
                    for (int e = 0; e < 2; e++){
                        int n = ni*8 + cb + e;
                        if (n < len){
                            float f = acc[ni][rh*2+e];
                            float ex = __expf(f - mx);
                            se += ex;
                            sw = fmaf(ex, f, sw);
                        }
                    }
                }
            }
            se += __shfl_xor_sync(0xffffffffu, se, 1);
            sw += __shfl_xor_sync(0xffffffffu, sw, 1);
            se += __shfl_xor_sync(0xffffffffu, se, 2);
            sw += __shfl_xor_sync(0xffffffffu, sw, 2);
            if ((lane & 3) == 0){
                int v = t*128 + r0 + (lane >> 2) + rh*8;
                if (v < VM1) out[(size_t)b*VM1 + v] = sw/se + (rh ? ad8 : ad0);
            }
        }
    }
}

// ---------------- host side ----------------
static float* symaddr(const void* sym){
    void* p = nullptr;
    cudaGetSymbolAddress(&p, sym);
    return (float*)p;
}

extern "C" void kernel_launch(void* const* d_in, const int* in_sizes, int n_in,
                              void* d_out, int out_size){
    (void)in_sizes; (void)n_in; (void)out_size;
    const int*   items  = (const int*)  d_in[0];
    const float* A      = (const float*)d_in[1];
    const int*   mask   = (const int*)  d_in[2];
    const float* emb    = (const float*)d_in[3];
    const float* w_ih   = (const float*)d_in[4];
    const float* w_hh   = (const float*)d_in[5];
    const float* b_ih   = (const float*)d_in[6];
    const float* b_hh   = (const float*)d_in[7];
    const float* b_iah  = (const float*)d_in[8];
    const float* b_oah  = (const float*)d_in[9];
    const float* W_ein  = (const float*)d_in[10];
    const float* b_ein  = (const float*)d_in[11];
    const float* W_eout = (const float*)d_in[12];
    const float* b_eout = (const float*)d_in[13];
    const float* W_one  = (const float*)d_in[14];
    const float* b_one  = (const float*)d_in[15];
    const float* W_two  = (const float*)d_in[16];
    const float* b_two  = (const float*)d_in[17];
    const float* w_three= (const float*)d_in[18];
    const float* W_tr   = (const float*)d_in[19];
    const float* b_tr   = (const float*)d_in[20];
    const float* W_t    = (const float*)d_in[21];
    float* out = (float*)d_out;

    float* Xcat = symaddr(g_Xcat);
    float* Wcat = symaddr(g_Wcat);
    float* bc   = symaddr(g_bc);
    float* T    = symaddr(g_T);
    float* hid  = symaddr(g_hidden);
    float* q2qt = symaddr(g_q2qt);
    float* a    = symaddr(g_a);

    static int init_done = 0;
    if (!init_done){
        cudaFuncSetAttribute(k_scores_mma, cudaFuncAttributeMaxDynamicSharedMemorySize, SC_BYTES);
        init_done = 1;
    }

    // one-time preps (serial, single stream — measured fastest)
    {
        dim3 g(2, 6);
        k_prep_wa<<<g, 256>>>(w_ih, W_ein, W_eout);
    }
    k_prep_wcat2<<<512, 128>>>(w_ih, w_hh, b_ih, b_hh, b_ein, b_eout, b_iah, b_oah);
    k_prep_emb<<<NT_, 256>>>(emb);
    k_gather<<<R_, H_>>>(items, emb, A);

    // 2 GNN steps: prop2 -> fast combined GEMM -> gate
    for (int step = 0; step < 2; step++){
        k_prop2<<<R_, H_>>>(A);
        dim3 gt(8, 7);
        k_gemm_f<<<gt, 256>>>(Xcat, Wcat, Wcat, 512, bc, nullptr, T, R_, KX, 512);
        k_gate2<<<R_, H_>>>();
    }

    // attention head: one GEMM produces [q2 | qt]
    {
        dim3 gq(4, 7);
        k_gemm_f<<<gq, 256>>>(hid, W_two, W_t, 128, b_two, nullptr, q2qt, R_, H_, 256);
    }
    k_alpha2<<<B_, H_>>>(mask, w_three, W_one, b_one, W_tr, b_tr);
    k_pack_tc<<<B_, 64>>>(a);

    // HMMA vocab scoring
    k_scores_mma<<<NT_, 256, SC_BYTES>>>(out);
}

// round 14
// speedup vs baseline: 1.3428x; 1.1451x over previous
#include <cuda_runtime.h>
#include <cuda_bf16.h>
#include <math.h>

// Problem constants
#define B_  16
#define N_  50
#define H_  128
#define V_  40000
#define VM1 39999      // V-1 rows of b_emb / output columns
#define R_  (B_*N_)    // 800 rows
#define NT_ 313        // ceil(VM1/128) vocab tiles (128 rows each)
#define KX  400        // padded Xcat/Wcat K (386 used)

// ---------------- scratch (static __device__, no allocs) ----------------
__device__ float g_hidden[R_*H_];
__device__ float g_Xcat  [R_*KX];      // [AHin(128) | AHout(128) | hidden(128) | rsin | rsout | pad]
__device__ float g_Wcat  [512*KX];
__device__ float g_bc    [512];
__device__ float g_T     [R_*512];
__device__ float g_q2qt  [R_*256];     // cols 0..127 = q2, cols 128..255 = qt
__device__ float g_a     [B_*H_];
// HMMA staging: bf16 hi/lo split, ldmatrix XOR-chunk swizzled layouts
__device__ unsigned char g_embh[(size_t)NT_*32768];
__device__ unsigned char g_embl[(size_t)NT_*32768];
__device__ unsigned char g_qbh [B_*16384];
__device__ unsigned char g_qbl [B_*16384];
__device__ int g_len[B_];

// ---------------- small helpers ----------------
__device__ __forceinline__ float sigmoidf_(float x){ return 1.f/(1.f+expf(-x)); }

__device__ __forceinline__ unsigned smem_u32(const void* p){
    unsigned a;
    asm("{ .reg .u64 t; cvta.to.shared.u64 t, %1; cvt.u32.u64 %0, t; }" : "=r"(a) : "l"(p));
    return a;
}
__device__ __forceinline__ unsigned long long pack2(float x, float y){
    unsigned long long r;
    asm("mov.b64 %0, {%1, %2};" : "=l"(r) : "f"(x), "f"(y));
    return r;
}
__device__ __forceinline__ unsigned long long fma2(unsigned long long a,
                                                   unsigned long long b,
                                                   unsigned long long c){
    unsigned long long d;
    asm("fma.rn.f32x2 %0, %1, %2, %3;" : "=l"(d) : "l"(a), "l"(b), "l"(c));
    return d;
}
__device__ __forceinline__ float lo2(unsigned long long u){
    return __uint_as_float((unsigned)(u & 0xffffffffULL));
}
__device__ __forceinline__ float hi2(unsigned long long u){
    return __uint_as_float((unsigned)(u >> 32));
}
__device__ __forceinline__ unsigned bf16pair(float a, float b){
    __nv_bfloat162 t = __floats2bfloat162_rn(a, b);
    return *reinterpret_cast<unsigned*>(&t);
}
__device__ __forceinline__ float bf16of(float x){
    return __bfloat162float(__float2bfloat16(x));
}
__device__ __forceinline__ void ldsm4(unsigned& r0, unsigned& r1, unsigned& r2, unsigned& r3,
                                      unsigned addr){
    asm volatile("ldmatrix.sync.aligned.m8n8.x4.shared.b16 {%0,%1,%2,%3}, [%4];"
                 : "=r"(r0),"=r"(r1),"=r"(r2),"=r"(r3) : "r"(addr));
}
__device__ __forceinline__ void mma16816(float* c, unsigned a0, unsigned a1, unsigned a2,
                                         unsigned a3, unsigned b0, unsigned b1){
    asm volatile(
        "mma.sync.aligned.m16n8k16.row.col.f32.bf16.bf16.f32 "
        "{%0,%1,%2,%3}, {%4,%5,%6,%7}, {%8,%9}, {%0,%1,%2,%3};"
        : "+f"(c[0]), "+f"(c[1]), "+f"(c[2]), "+f"(c[3])
        : "r"(a0), "r"(a1), "r"(a2), "r"(a3), "r"(b0), "r"(b1));
}

// ---------------- fast SGEMM: 128x64 tile, 256 threads, 8r x 4j per thread ----------------
// out[r,j] = sum_k X[r,k]*W[j,k] (+bias). W row j from W0 (j<Jsplit) or W1. K%16==0.
__global__ void __launch_bounds__(256)
k_gemm_f(const float* __restrict__ X, const float* __restrict__ W0,
         const float* __restrict__ W1, int Jsplit,
         const float* __restrict__ bias0, const float* __restrict__ bias1,
         float* __restrict__ out, int R, int K, int J){
    __shared__ __align__(16) float xs[16][132];
    __shared__ __align__(16) float ws[16][68];
    const int tid = threadIdx.x;
    const int tr = tid >> 4, tc = tid & 15;
    const int r0 = blockIdx.y << 7, j0 = blockIdx.x << 6;
    unsigned long long acc[4][4];
    #pragma unroll
    for (int p=0;p<4;p++)
        #pragma unroll
        for (int j=0;j<4;j++) acc[p][j] = 0ULL;

    for (int kc = 0; kc < K; kc += 16){
        // stage X chunk: 128 rows x 16 k (512 float4 loads)
        #pragma unroll
        for (int it = 0; it < 2; it++){
            int idx = tid + (it<<8);
            int rr = idx >> 2, kq = idx & 3;
            float4 v = make_float4(0.f,0.f,0.f,0.f);
            if (r0 + rr < R)
                v = *reinterpret_cast<const float4*>(X + (size_t)(r0+rr)*K + kc + (kq<<2));
            xs[(kq<<2)+0][rr] = v.x;
            xs[(kq<<2)+1][rr] = v.y;
            xs[(kq<<2)+2][rr] = v.z;
            xs[(kq<<2)+3][rr] = v.w;
        }
        // stage W chunk: 64 j x 16 k (256 float4 loads)
        {
            int jj = tid >> 2, kq = tid & 3;
            int j = j0 + jj;
            float4 v = make_float4(0.f,0.f,0.f,0.f);
            if (j < J){
                const float* Wr = (j < Jsplit) ? (W0 + (size_t)j*K)
                                               : (W1 + (size_t)(j-Jsplit)*K);
                v = *reinterpret_cast<const float4*>(Wr + kc + (kq<<2));
            }
            ws[(kq<<2)+0][jj] = v.x;
            ws[(kq<<2)+1][jj] = v.y;
            ws[(kq<<2)+2][jj] = v.z;
            ws[(kq<<2)+3][jj] = v.w;
        }
        __syncthreads();
        #pragma unroll
        for (int kk = 0; kk < 16; kk++){
            float4 xA = *reinterpret_cast<const float4*>(&xs[kk][tr<<3]);
            float4 xB = *reinterpret_cast<const float4*>(&xs[kk][(tr<<3)+4]);
            float4 wv = *reinterpret_cast<const float4*>(&ws[kk][tc<<2]);
            unsigned long long xu0 = pack2(xA.x, xA.y);
            unsigned long long xu1 = pack2(xA.z, xA.w);
            unsigned long long xu2 = pack2(xB.x, xB.y);
            unsigned long long xu3 = pack2(xB.z, xB.w);
            float wf[4] = {wv.x, wv.y, wv.z, wv.w};
            #pragma unroll
            for (int j = 0; j < 4; j++){
                unsigned long long wb = pack2(wf[j], wf[j]);
                acc[0][j] = fma2(xu0, wb, acc[0][j]);
                acc[1][j] = fma2(xu1, wb, acc[1][j]);
                acc[2][j] = fma2(xu2, wb, acc[2][j]);
                acc[3][j] = fma2(xu3, wb, acc[3][j]);
            }
        }
        __syncthreads();
    }
    #pragma unroll
    for (int p = 0; p < 4; p++){
        #pragma unroll
        for (int e = 0; e < 2; e++){
            int r = r0 + (tr<<3) + (p<<1) + e;
            if (r >= R) continue;
            #pragma unroll
            for (int j = 0; j < 4; j++){
                int jj = j0 + (tc<<2) + j;
                if (jj >= J) continue;
                float bv = (jj < Jsplit) ? (bias0 ? bias0[jj] : 0.f)
                                         : (bias1 ? bias1[jj - Jsplit] : 0.f);
                float val = e ? hi2(acc[p][j]) : lo2(acc[p][j]);
                out[(size_t)r*J + jj] = val + bv;
            }
        }
    }
}

// ---------------- prep A: WA/WB = w_ih halves @ W_ein/W_eout -> Wcat cols [0:256) ----------------
__global__ void k_prep_wa(const float* __restrict__ w_ih, const float* __restrict__ W_ein,
                          const float* __restrict__ W_eout){
    __shared__ float xs1[16][65], xs2[16][65];
    __shared__ float ws1[16][65], ws2[16][65];
    int tid = threadIdx.x;
    int tr = tid >> 4, tc = tid & 15;
    int j0 = blockIdx.y << 6, h0 = blockIdx.x << 6;
    float acc1[4][4] = {}, acc2[4][4] = {};
    for (int kc = 0; kc < H_; kc += 16){
        for (int t = tid; t < 1024; t += 256){
            int rr = t >> 4, kk = t & 15;
            int j = j0 + rr;
            xs1[kk][rr] = (j < 384) ? w_ih[(size_t)j*256 + kc + kk]       : 0.f;
            xs2[kk][rr] = (j < 384) ? w_ih[(size_t)j*256 + 128 + kc + kk] : 0.f;
        }
        for (int t = tid; t < 1024; t += 256){
            int jj = t >> 4, kk = t & 15;
            ws1[kk][jj] = W_ein [(size_t)(kc+kk)*H_ + h0 + jj];
            ws2[kk][jj] = W_eout[(size_t)(kc+kk)*H_ + h0 + jj];
        }
        __syncthreads();
        #pragma unroll
        for (int kk = 0; kk < 16; kk++){
            float x1[4], x2[4], w1[4], w2[4];
            #pragma unroll
            for (int i=0;i<4;i++){ x1[i]=xs1[kk][(tr<<2)+i]; x2[i]=xs2[kk][(tr<<2)+i]; }
            #pragma unroll
            for (int j=0;j<4;j++){ w1[j]=ws1[kk][(tc<<2)+j]; w2[j]=ws2[kk][(tc<<2)+j]; }
            #pragma unroll
            for (int i=0;i<4;i++)
                #pragma unroll
                for (int j=0;j<4;j++){
                    acc1[i][j] = fmaf(x1[i], w1[j], acc1[i][j]);
                    acc2[i][j] = fmaf(x2[i], w2[j], acc2[i][j]);
                }
        }
        __syncthreads();
    }
    #pragma unroll
    for (int i=0;i<4;i++){
        int j = j0 + (tr<<2) + i;
        if (j >= 384) continue;
        #pragma unroll
        for (int q=0;q<4;q++){
            int h = h0 + (tc<<2) + q;
            g_Wcat[(size_t)j*KX + h]       = acc1[i][q];
            g_Wcat[(size_t)j*KX + 128 + h] = acc2[i][q];
        }
    }
}

// ---------------- prep B: Wcat cols [256:384) = w_hh, cols 384/385 = uin/uout, bias bc ----------------
__global__ void k_prep_wcat2(const float* __restrict__ w_ih, const float* __restrict__ w_hh,
                             const float* __restrict__ b_ih, const float* __restrict__ b_hh,
                             const float* __restrict__ b_ein, const float* __restrict__ b_eout,
                             const float* __restrict__ b_iah, const float* __restrict__ b_oah){
    int j = blockIdx.x, h = threadIdx.x;
    int jrow = (j < 384) ? j : 256 + (j - 384);
    g_Wcat[(size_t)j*KX + 256 + h] = w_hh[(size_t)jrow*H_ + h];
    __shared__ float4 red[128];
    float4 v = make_float4(0.f,0.f,0.f,0.f);
    if (j < 384){
        float p1 = w_ih[(size_t)j*256 + h];
        float p2 = w_ih[(size_t)j*256 + 128 + h];
        v = make_float4(p1*b_ein[h], p2*b_eout[h], p1*b_iah[h], p2*b_oah[h]);
    }
    red[h] = v;
    for (int s = 64; s; s >>= 1){
        __syncthreads();
        if (h < s){
            float4 o = red[h+s];
            red[h].x += o.x; red[h].y += o.y; red[h].z += o.z; red[h].w += o.w;
        }
    }
    __syncthreads();
    if (h == 0){
        float4 t = red[0];
        g_Wcat[(size_t)j*KX + 384] = (j < 384) ? t.x : 0.f;
        g_Wcat[(size_t)j*KX + 385] = (j < 384) ? t.y : 0.f;
        g_bc[j] = (j < 384) ? (b_ih[j] + b_hh[j] + t.z + t.w) : b_hh[jrow];
    }
    if (h < 14) g_Wcat[(size_t)j*KX + 386 + h] = 0.f;
}

// ---------------- gather + rowsums + Xcat init ----------------
__global__ void k_gather(const int* __restrict__ items, const float* __restrict__ emb,
                         const float* __restrict__ A){
    int r = blockIdx.x, tid = threadIdx.x;
    float v = emb[(size_t)items[r]*H_ + tid];
    g_hidden[r*H_ + tid] = v;
    g_Xcat[(size_t)r*KX + 256 + tid] = v;
    int lane = tid & 31, wid = tid >> 5;
    if (wid < 2){
        float s = 0.f;
        for (int m = lane; m < N_; m += 32) s += A[(size_t)r*2*N_ + wid*N_ + m];
        for (int d = 16; d; d >>= 1) s += __shfl_xor_sync(0xffffffffu, s, d);
        if (lane == 0) g_Xcat[(size_t)r*KX + 384 + wid] = s;
    }
    if (tid >= 64 && tid < 78) g_Xcat[(size_t)r*KX + 386 + (tid - 64)] = 0.f;
}

// ---------------- prop2: AHin/AHout = A @ hidden -> Xcat[:,0:256) ----------------
__global__ void k_prop2(const float* __restrict__ A){
    int r = blockIdx.x;
    int b = r / N_;
    int h = threadIdx.x;
    __shared__ float arow[2*N_];
    if (h < 2*N_) arow[h] = A[(size_t)r*2*N_ + h];
    __syncthreads();
    float sin = 0.f, sout = 0.f;
    #pragma unroll 10
    for (int m = 0; m < N_; m++){
        sin  = fmaf(arow[m],     g_hidden[(b*N_+m)*H_ + h], sin);
        sout = fmaf(arow[N_+m],  g_hidden[(b*N_+m)*H_ + h], sout);
    }
    g_Xcat[(size_t)r*KX + h]       = sin;
    g_Xcat[(size_t)r*KX + 128 + h] = sout;
}

// ---------------- GRU gate from T; updates hidden + Xcat hidden slot ----------------
__global__ void k_gate2(){
    int r = blockIdx.x, h = threadIdx.x;
    float sr  = g_T[(size_t)r*512 + h];
    float si  = g_T[(size_t)r*512 + 128 + h];
    float sn  = g_T[(size_t)r*512 + 256 + h];
    float hnv = g_T[(size_t)r*512 + 384 + h];
    float rg = sigmoidf_(sr);
    float ig = sigmoidf_(si);
    float ng = tanhf(sn - hnv + rg * hnv);
    float hv = g_hidden[(size_t)r*H_ + h];
    float nh = ng + ig * (hv - ng);
    g_hidden[(size_t)r*H_ + h] = nh;
    g_Xcat[(size_t)r*KX + 256 + h] = nh;
}

// ---------------- fused attention head: len, ht, q1, alpha, cat, a ----------------
__global__ void k_alpha2(const int* __restrict__ mask, const float* __restrict__ w3,
                         const float* __restrict__ W_one, const float* __restrict__ b_one,
                         const float* __restrict__ W_tr,  const float* __restrict__ b_tr){
    int b = blockIdx.x, tid = threadIdx.x;
    __shared__ int slen;
    __shared__ float hts[128], q1s[128], logits[N_], cats[256];
    int warp = tid >> 5, lane = tid & 31;
    if (tid == 0){
        int s = 0;
        for (int n = 0; n < N_; n++) s += mask[b*N_+n];
        slen = s;
        g_len[b] = s;
    }
    __syncthreads();
    const int len = slen;
    float htv = g_hidden[(size_t)(b*N_ + len - 1)*H_ + tid];
    hts[tid] = htv;
    __syncthreads();
    float q1 = b_one[tid];
    #pragma unroll 8
    for (int k = 0; k < H_; k++) q1 = fmaf(hts[k], W_one[(size_t)tid*H_ + k], q1);
    q1s[tid] = q1;
    __syncthreads();
    for (int n = warp; n < len; n += 4){
        float s = 0.f;
        for (int hh = lane; hh < H_; hh += 32){
            float x = q1s[hh] + g_q2qt[(size_t)(b*N_+n)*256 + hh];
            s += sigmoidf_(x) * w3[hh];
        }
        for (int d = 16; d; d >>= 1) s += __shfl_xor_sync(0xffffffffu, s, d);
        if (lane == 0) logits[n] = s;
    }
    __syncthreads();
    float mx = -3.0e38f;
    for (int n = 0; n < len; n++) mx = fmaxf(mx, logits[n]);
    float denom = 0.f;
    for (int n = 0; n < len; n++) denom += expf(logits[n]-mx);
    float s = 0.f;
    for (int n = 0; n < len; n++)
        s = fmaf(expf(logits[n]-mx), g_hidden[(size_t)(b*N_+n)*H_ + tid], s);
    cats[tid] = s / denom;
    cats[128 + tid] = htv;
    __syncthreads();
    float av = b_tr[tid];
    #pragma unroll 8
    for (int k = 0; k < 256; k++) av = fmaf(cats[k], W_tr[(size_t)tid*256 + k], av);
    g_a[b*H_ + tid] = av;
}

// ---------------- prep: emb -> bf16 hi/lo tiles, coalesced (warp = chunks x rows) ----------------
__global__ void k_prep_emb(const float* __restrict__ emb){
    int t = blockIdx.x;
    int c  = threadIdx.x & 15;       // chunk 0..15
    int r8 = threadIdx.x >> 4;       // 0..15
    uint4* dh = reinterpret_cast<uint4*>(g_embh);
    uint4* dl = reinterpret_cast<uint4*>(g_embl);
    #pragma unroll
    for (int it = 0; it < 8; it++){
        int r = r8 + (it << 4);      // 0..127
        int vg = t*128 + r;
        bool ok = vg < VM1;
        const float4* src = reinterpret_cast<const float4*>(emb + (size_t)(vg+1)*H_);
        float4 f0 = ok ? src[2*c]   : make_float4(0.f,0.f,0.f,0.f);
        float4 f1 = ok ? src[2*c+1] : make_float4(0.f,0.f,0.f,0.f);
        uint4 hi, lo;
        hi.x = bf16pair(f0.x, f0.y); hi.y = bf16pair(f0.z, f0.w);
        hi.z = bf16pair(f1.x, f1.y); hi.w = bf16pair(f1.z, f1.w);
        lo.x = bf16pair(f0.x - bf16of(f0.x), f0.y - bf16of(f0.y));
        lo.y = bf16pair(f0.z - bf16of(f0.z), f0.w - bf16of(f0.w));
        lo.z = bf16pair(f1.x - bf16of(f1.x), f1.y - bf16of(f1.y));
        lo.w = bf16pair(f1.z - bf16of(f1.z), f1.w - bf16of(f1.w));
        size_t o = ((size_t)t*128 + r)*16 + (c ^ (r & 7));
        dh[o] = hi;
        dl[o] = lo;
    }
}

// ---------------- pack qt/a -> per-batch B tiles; a at column len ----------------
__global__ void k_pack_tc(const float* __restrict__ a){
    int b = blockIdx.x, n = threadIdx.x;   // 64 threads
    int len = g_len[b];
    const float* src = (n < len) ? (g_q2qt + (size_t)(b*N_+n)*256 + 128)
                 : (n == len)    ? (a + (size_t)b*H_) : nullptr;
    uint4* dh = reinterpret_cast<uint4*>(g_qbh);
    uint4* dl = reinterpret_cast<uint4*>(g_qbl);
    size_t rb = ((size_t)b*64 + n)*16;
    #pragma unroll
    for (int c = 0; c < 16; c++){
        float4 f0 = src ? *reinterpret_cast<const float4*>(src + c*8)     : make_float4(0.f,0.f,0.f,0.f);
        float4 f1 = src ? *reinterpret_cast<const float4*>(src + c*8 + 4) : make_float4(0.f,0.f,0.f,0.f);
        uint4 hi, lo;
        hi.x = bf16pair(f0.x, f0.y); hi.y = bf16pair(f0.z, f0.w);
        hi.z = bf16pair(f1.x, f1.y); hi.w = bf16pair(f1.z, f1.w);
        lo.x = bf16pair(f0.x - bf16of(f0.x), f0.y - bf16of(f0.y));
        lo.y = bf16pair(f0.z - bf16of(f0.z), f0.w - bf16of(f0.w));
        lo.z = bf16pair(f1.x - bf16of(f1.x), f1.y - bf16of(f1.y));
        lo.w = bf16pair(f1.z - bf16of(f1.z), f1.w - bf16of(f1.w));
        size_t o = rb + (c ^ (n & 7));
        dh[o] = hi;
        dl[o] = lo;
    }
}

// ---------------- HMMA vocab scoring ----------------
// Mainloop restructured: outer ni2 with ONE len-guard each (4 branch regions/batch
// instead of ~96 unrolled-guard regions), inner ks fully unrolled and branchless.
// A fragments re-loaded per ni2 (cheap ldsm); acc indices all static.
#define SC_AH 0
#define SC_AL 32768
#define SC_BH 65536
#define SC_BL 81920
#define SC_BYTES 98304

__global__ void __launch_bounds__(256, 2)
k_scores_mma(float* __restrict__ out){
    extern __shared__ char sm[];
    unsigned sbase = smem_u32(sm);
    const int tid = threadIdx.x, wid = tid >> 5, lane = tid & 31;
    const int t = blockIdx.x;

    // stage A tiles (pre-swizzled): 32KB hi + 32KB lo
    {
        const uint4* sh = reinterpret_cast<const uint4*>(g_embh + (size_t)t*32768);
        const uint4* sl = reinterpret_cast<const uint4*>(g_embl + (size_t)t*32768);
        uint4* dh = reinterpret_cast<uint4*>(sm + SC_AH);
        uint4* dl = reinterpret_cast<uint4*>(sm + SC_AL);
        #pragma unroll
        for (int i = 0; i < 8; i++){
            dh[tid + (i<<8)] = sh[tid + (i<<8)];
            dl[tid + (i<<8)] = sl[tid + (i<<8)];
        }
    }

    const int r0   = wid << 4;
    const int rowA = r0 + (lane & 15);
    const int phA  = rowA & 7;
    const int hl   = lane >> 4;
    const unsigned baseAh = sbase + SC_AH + rowA*256;
    const unsigned baseAl = sbase + SC_AL + rowA*256;
    const int rowB = (lane & 15);
    const int phB0 = rowB & 7;

    for (int b = 0; b < B_; b++){
        __syncthreads();
        // stage B tiles (16KB hi + 16KB lo)
        {
            const uint4* sh = reinterpret_cast<const uint4*>(g_qbh + (size_t)b*16384);
            const uint4* sl = reinterpret_cast<const uint4*>(g_qbl + (size_t)b*16384);
            uint4* dh = reinterpret_cast<uint4*>(sm + SC_BH);
            uint4* dl = reinterpret_cast<uint4*>(sm + SC_BL);
            #pragma unroll
            for (int i = 0; i < 4; i++){
                dh[tid + (i<<8)] = sh[tid + (i<<8)];
                dl[tid + (i<<8)] = sl[tid + (i<<8)];
            }
        }
        __syncthreads();
        const int len = g_len[b];

        float acc[8][4];
        #pragma unroll
        for (int ni = 0; ni < 8; ni++)
            #pragma unroll
            for (int e = 0; e < 4; e++) acc[ni][e] = 0.f;

        // outer ni2: one uniform guard per 16-column pair; inner ks branchless
        #pragma unroll
        for (int ni2 = 0; ni2 < 4; ni2++){
            if (ni2*16 <= len){
                #pragma unroll
                for (int ks = 0; ks < 8; ks++){
                    unsigned offA = (unsigned)(((ks*2 + hl) ^ phA) << 4);
                    unsigned ah0,ah1,ah2,ah3, al0,al1,al2,al3;
                    ldsm4(ah0, ah1, ah2, ah3, baseAh + offA);
                    ldsm4(al0, al1, al2, al3, baseAl + offA);
                    unsigned offB = (unsigned)((ni2*16 + rowB)*256 + (((ks*2 + hl) ^ phB0) << 4));
                    unsigned q0,q1,q2,q3, p0,p1,p2,p3;
                    ldsm4(q0,q1,q2,q3, sbase + SC_BH + offB);
                    ldsm4(p0,p1,p2,p3, sbase + SC_BL + offB);
                    // even tile (2*ni2): B cols pair (q0,q2)/(p0,p2)
                    mma16816(acc[2*ni2],   ah0,ah1,ah2,ah3, q0, q2);
                    mma16816(acc[2*ni2],   ah0,ah1,ah2,ah3, p0, p2);
                    mma16816(acc[2*ni2],   al0,al1,al2,al3, q0, q2);
                    // odd tile (2*ni2+1): (q1,q3)/(p1,p3)
                    mma16816(acc[2*ni2+1], ah0,ah1,ah2,ah3, q1, q3);
                    mma16816(acc[2*ni2+1], ah0,ah1,ah2,ah3, p1, p3);
                    mma16816(acc[2*ni2+1], al0,al1,al2,al3, q1, q3);
                }
            }
        }

        // a-dot lives at column len: tile len>>3, in-tile col len&7
        float av0 = 0.f, av8 = 0.f;
        #pragma unroll
        for (int ni = 0; ni < 8; ni++){
            if (ni == (len >> 3)){
                av0 = (len & 1) ? acc[ni][1] : acc[ni][0];
                av8 = (len & 1) ? acc[ni][3] : acc[ni][2];
            }
        }
        const int alane = (lane & ~3) | ((len & 7) >> 1);
        float ad0 = __shfl_sync(0xffffffffu, av0, alane);
        float ad8 = __shfl_sync(0xffffffffu, av8, alane);

        const int cb = (lane & 3) << 1;
        #pragma unroll
        for (int rh = 0; rh < 2; rh++){
            float mx = -3.0e38f;
            #pragma unroll
            for (int ni = 0; ni < 8; ni++){
                if (ni*8 < len){
                    #pragma unroll
                    for (int e = 0; e < 2; e++){
                        int n = ni*8 + cb + e;
                        if (n < len) mx = fmaxf(mx, acc[ni][rh*2+e]);
                    }
                }
            }
            mx = fmaxf(mx, __shfl_xor_sync(0xffffffffu, mx, 1));
            mx = fmaxf(mx, __shfl_xor_sync(0xffffffffu, mx, 2));
            float se = 0.f, sw = 0.f;
            #pragma unroll
            for (int ni = 0; ni < 8; ni++){
                if (ni*8 < len){
                    #pragma unroll
                    for (int e = 0; e < 2; e++){
                        int n = ni*8 + cb + e;
                        if (n < len){
                            float f = acc[ni][rh*2+e];
                            float ex = __expf(f - mx);
                            se += ex;
                            sw = fmaf(ex, f, sw);
                        }
                    }
                }
            }
            se += __shfl_xor_sync(0xffffffffu, se, 1);
            sw += __shfl_xor_sync(0xffffffffu, sw, 1);
            se += __shfl_xor_sync(0xffffffffu, se, 2);
            sw += __shfl_xor_sync(0xffffffffu, sw, 2);
            if ((lane & 3) == 0){
                int v = t*128 + r0 + (lane >> 2) + rh*8;
                if (v < VM1) out[(size_t)b*VM1 + v] = sw/se + (rh ? ad8 : ad0);
            }
        }
    }
}

// ---------------- host side ----------------
static float* symaddr(const void* sym){
    void* p = nullptr;
    cudaGetSymbolAddress(&p, sym);
    return (float*)p;
}

extern "C" void kernel_launch(void* const* d_in, const int* in_sizes, int n_in,
                              void* d_out, int out_size){
    (void)in_sizes; (void)n_in; (void)out_size;
    const int*   items  = (const int*)  d_in[0];
    const float* A      = (const float*)d_in[1];
    const int*   mask   = (const int*)  d_in[2];
    const float* emb    = (const float*)d_in[3];
    const float* w_ih   = (const float*)d_in[4];
    const float* w_hh   = (const float*)d_in[5];
    const float* b_ih   = (const float*)d_in[6];
    const float* b_hh   = (const float*)d_in[7];
    const float* b_iah  = (const float*)d_in[8];
    const float* b_oah  = (const float*)d_in[9];
    const float* W_ein  = (const float*)d_in[10];
    const float* b_ein  = (const float*)d_in[11];
    const float* W_eout = (const float*)d_in[12];
    const float* b_eout = (const float*)d_in[13];
    const float* W_one  = (const float*)d_in[14];
    const float* b_one  = (const float*)d_in[15];
    const float* W_two  = (const float*)d_in[16];
    const float* b_two  = (const float*)d_in[17];
    const float* w_three= (const float*)d_in[18];
    const float* W_tr   = (const float*)d_in[19];
    const float* b_tr   = (const float*)d_in[20];
    const float* W_t    = (const float*)d_in[21];
    float* out = (float*)d_out;

    float* Xcat = symaddr(g_Xcat);
    float* Wcat = symaddr(g_Wcat);
    float* bc   = symaddr(g_bc);
    float* T    = symaddr(g_T);
    float* hid  = symaddr(g_hidden);
    float* q2qt = symaddr(g_q2qt);
    float* a    = symaddr(g_a);

    static int init_done = 0;
    if (!init_done){
        cudaFuncSetAttribute(k_scores_mma, cudaFuncAttributeMaxDynamicSharedMemorySize, SC_BYTES);
        init_done = 1;
    }

    // one-time preps (serial, single stream — measured fastest)
    {
        dim3 g(2, 6);
        k_prep_wa<<<g, 256>>>(w_ih, W_ein, W_eout);
    }
    k_prep_wcat2<<<512, 128>>>(w_ih, w_hh, b_ih, b_hh, b_ein, b_eout, b_iah, b_oah);
    k_prep_emb<<<NT_, 256>>>(emb);
    k_gather<<<R_, H_>>>(items, emb, A);

    // 2 GNN steps: prop2 -> fast combined GEMM -> gate
    for (int step = 0; step < 2; step++){
        k_prop2<<<R_, H_>>>(A);
        dim3 gt(8, 7);
        k_gemm_f<<<gt, 256>>>(Xcat, Wcat, Wcat, 512, bc, nullptr, T, R_, KX, 512);
        k_gate2<<<R_, H_>>>();
    }

    // attention head: one GEMM produces [q2 | qt]
    {
        dim3 gq(4, 7);
        k_gemm_f<<<gq, 256>>>(hid, W_two, W_t, 128, b_two, nullptr, q2qt, R_, H_, 256);
    }
    k_alpha2<<<B_, H_>>>(mask, w_three, W_one, b_one, W_tr, b_tr);
    k_pack_tc<<<B_, 64>>>(a);

    // HMMA vocab scoring
    k_scores_mma<<<NT_, 256, SC_BYTES>>>(out);
}

// round 15
// speedup vs baseline: 1.5307x; 1.1399x over previous
#include <cuda_runtime.h>
#include <cuda_bf16.h>
#include <math.h>

// Problem constants
#define B_  16
#define N_  50
#define H_  128
#define V_  40000
#define VM1 39999      // V-1 rows of b_emb / output columns
#define R_  (B_*N_)    // 800 rows
#define NT_ 313        // ceil(VM1/128) vocab tiles (128 rows each)
#define KX  400        // padded Xcat/Wcat K (386 used)

// ---------------- scratch (static __device__, no allocs) ----------------
__device__ float g_hidden[R_*H_];
__device__ float g_Xcat  [R_*KX];      // [AHin(128) | AHout(128) | hidden(128) | rsin | rsout | pad]
__device__ float g_Wcat  [512*KX];
__device__ float g_bc    [512];
__device__ float g_T     [R_*512];
__device__ float g_q2qt  [R_*256];     // cols 0..127 = q2, cols 128..255 = qt
__device__ float g_a     [B_*H_];
// HMMA staging: bf16 hi/lo split, ldmatrix XOR-chunk swizzled layouts
__device__ unsigned char g_embh[(size_t)NT_*32768];
__device__ unsigned char g_embl[(size_t)NT_*32768];
__device__ unsigned char g_qbh [B_*16384];
__device__ unsigned char g_qbl [B_*16384];
__device__ int g_len[B_];

// ---------------- small helpers ----------------
__device__ __forceinline__ float sigmoidf_(float x){ return 1.f/(1.f+expf(-x)); }

__device__ __forceinline__ unsigned smem_u32(const void* p){
    unsigned a;
    asm("{ .reg .u64 t; cvta.to.shared.u64 t, %1; cvt.u32.u64 %0, t; }" : "=r"(a) : "l"(p));
    return a;
}
__device__ __forceinline__ unsigned long long pack2(float x, float y){
    unsigned long long r;
    asm("mov.b64 %0, {%1, %2};" : "=l"(r) : "f"(x), "f"(y));
    return r;
}
__device__ __forceinline__ unsigned long long fma2(unsigned long long a,
                                                   unsigned long long b,
                                                   unsigned long long c){
    unsigned long long d;
    asm("fma.rn.f32x2 %0, %1, %2, %3;" : "=l"(d) : "l"(a), "l"(b), "l"(c));
    return d;
}
__device__ __forceinline__ float lo2(unsigned long long u){
    return __uint_as_float((unsigned)(u & 0xffffffffULL));
}
__device__ __forceinline__ float hi2(unsigned long long u){
    return __uint_as_float((unsigned)(u >> 32));
}
__device__ __forceinline__ unsigned bf16pair(float a, float b){
    __nv_bfloat162 t = __floats2bfloat162_rn(a, b);
    return *reinterpret_cast<unsigned*>(&t);
}
__device__ __forceinline__ float bf16of(float x){
    return __bfloat162float(__float2bfloat16(x));
}
__device__ __forceinline__ void ldsm4(unsigned& r0, unsigned& r1, unsigned& r2, unsigned& r3,
                                      unsigned addr){
    asm volatile("ldmatrix.sync.aligned.m8n8.x4.shared.b16 {%0,%1,%2,%3}, [%4];"
                 : "=r"(r0),"=r"(r1),"=r"(r2),"=r"(r3) : "r"(addr));
}
__device__ __forceinline__ void mma16816(float* c, unsigned a0, unsigned a1, unsigned a2,
                                         unsigned a3, unsigned b0, unsigned b1){
    asm volatile(
        "mma.sync.aligned.m16n8k16.row.col.f32.bf16.bf16.f32 "
        "{%0,%1,%2,%3}, {%4,%5,%6,%7}, {%8,%9}, {%0,%1,%2,%3};"
        : "+f"(c[0]), "+f"(c[1]), "+f"(c[2]), "+f"(c[3])
        : "r"(a0), "r"(a1), "r"(a2), "r"(a3), "r"(b0), "r"(b1));
}

// ---------------- fast SGEMM: 128x64 tile, 256 threads, 8r x 4j per thread ----------------
// out[r,j] = sum_k X[r,k]*W[j,k] (+bias). W row j from W0 (j<Jsplit) or W1. K%16==0.
__global__ void __launch_bounds__(256)
k_gemm_f(const float* __restrict__ X, const float* __restrict__ W0,
         const float* __restrict__ W1, int Jsplit,
         const float* __restrict__ bias0, const float* __restrict__ bias1,
         float* __restrict__ out, int R, int K, int J){
    __shared__ __align__(16) float xs[16][132];
    __shared__ __align__(16) float ws[16][68];
    const int tid = threadIdx.x;
    const int tr = tid >> 4, tc = tid & 15;
    const int r0 = blockIdx.y << 7, j0 = blockIdx.x << 6;
    unsigned long long acc[4][4];
    #pragma unroll
    for (int p=0;p<4;p++)
        #pragma unroll
        for (int j=0;j<4;j++) acc[p][j] = 0ULL;

    for (int kc = 0; kc < K; kc += 16){
        // stage X chunk: 128 rows x 16 k (512 float4 loads)
        #pragma unroll
        for (int it = 0; it < 2; it++){
            int idx = tid + (it<<8);
            int rr = idx >> 2, kq = idx & 3;
            float4 v = make_float4(0.f,0.f,0.f,0.f);
            if (r0 + rr < R)
                v = *reinterpret_cast<const float4*>(X + (size_t)(r0+rr)*K + kc + (kq<<2));
            xs[(kq<<2)+0][rr] = v.x;
            xs[(kq<<2)+1][rr] = v.y;
            xs[(kq<<2)+2][rr] = v.z;
            xs[(kq<<2)+3][rr] = v.w;
        }
        // stage W chunk: 64 j x 16 k (256 float4 loads)
        {
            int jj = tid >> 2, kq = tid & 3;
            int j = j0 + jj;
            float4 v = make_float4(0.f,0.f,0.f,0.f);
            if (j < J){
                const float* Wr = (j < Jsplit) ? (W0 + (size_t)j*K)
                                               : (W1 + (size_t)(j-Jsplit)*K);
                v = *reinterpret_cast<const float4*>(Wr + kc + (kq<<2));
            }
            ws[(kq<<2)+0][jj] = v.x;
            ws[(kq<<2)+1][jj] = v.y;
            ws[(kq<<2)+2][jj] = v.z;
            ws[(kq<<2)+3][jj] = v.w;
        }
        __syncthreads();
        #pragma unroll
        for (int kk = 0; kk < 16; kk++){
            float4 xA = *reinterpret_cast<const float4*>(&xs[kk][tr<<3]);
            float4 xB = *reinterpret_cast<const float4*>(&xs[kk][(tr<<3)+4]);
            float4 wv = *reinterpret_cast<const float4*>(&ws[kk][tc<<2]);
            unsigned long long xu0 = pack2(xA.x, xA.y);
            unsigned long long xu1 = pack2(xA.z, xA.w);
            unsigned long long xu2 = pack2(xB.x, xB.y);
            unsigned long long xu3 = pack2(xB.z, xB.w);
            float wf[4] = {wv.x, wv.y, wv.z, wv.w};
            #pragma unroll
            for (int j = 0; j < 4; j++){
                unsigned long long wb = pack2(wf[j], wf[j]);
                acc[0][j] = fma2(xu0, wb, acc[0][j]);
                acc[1][j] = fma2(xu1, wb, acc[1][j]);
                acc[2][j] = fma2(xu2, wb, acc[2][j]);
                acc[3][j] = fma2(xu3, wb, acc[3][j]);
            }
        }
        __syncthreads();
    }
    #pragma unroll
    for (int p = 0; p < 4; p++){
        #pragma unroll
        for (int e = 0; e < 2; e++){
            int r = r0 + (tr<<3) + (p<<1) + e;
            if (r >= R) continue;
            #pragma unroll
            for (int j = 0; j < 4; j++){
                int jj = j0 + (tc<<2) + j;
                if (jj >= J) continue;
                float bv = (jj < Jsplit) ? (bias0 ? bias0[jj] : 0.f)
                                         : (bias1 ? bias1[jj - Jsplit] : 0.f);
                float val = e ? hi2(acc[p][j]) : lo2(acc[p][j]);
                out[(size_t)r*J + jj] = val + bv;
            }
        }
    }
}

// ---------------- prep A: WA/WB = w_ih halves @ W_ein/W_eout -> Wcat cols [0:256) ----------------
__global__ void k_prep_wa(const float* __restrict__ w_ih, const float* __restrict__ W_ein,
                          const float* __restrict__ W_eout){
    __shared__ float xs1[16][65], xs2[16][65];
    __shared__ float ws1[16][65], ws2[16][65];
    int tid = threadIdx.x;
    int tr = tid >> 4, tc = tid & 15;
    int j0 = blockIdx.y << 6, h0 = blockIdx.x << 6;
    float acc1[4][4] = {}, acc2[4][4] = {};
    for (int kc = 0; kc < H_; kc += 16){
        for (int t = tid; t < 1024; t += 256){
            int rr = t >> 4, kk = t & 15;
            int j = j0 + rr;
            xs1[kk][rr] = (j < 384) ? w_ih[(size_t)j*256 + kc + kk]       : 0.f;
            xs2[kk][rr] = (j < 384) ? w_ih[(size_t)j*256 + 128 + kc + kk] : 0.f;
        }
        for (int t = tid; t < 1024; t += 256){
            int jj = t >> 4, kk = t & 15;
            ws1[kk][jj] = W_ein [(size_t)(kc+kk)*H_ + h0 + jj];
            ws2[kk][jj] = W_eout[(size_t)(kc+kk)*H_ + h0 + jj];
        }
        __syncthreads();
        #pragma unroll
        for (int kk = 0; kk < 16; kk++){
            float x1[4], x2[4], w1[4], w2[4];
            #pragma unroll
            for (int i=0;i<4;i++){ x1[i]=xs1[kk][(tr<<2)+i]; x2[i]=xs2[kk][(tr<<2)+i]; }
            #pragma unroll
            for (int j=0;j<4;j++){ w1[j]=ws1[kk][(tc<<2)+j]; w2[j]=ws2[kk][(tc<<2)+j]; }
            #pragma unroll
            for (int i=0;i<4;i++)
                #pragma unroll
                for (int j=0;j<4;j++){
                    acc1[i][j] = fmaf(x1[i], w1[j], acc1[i][j]);
                    acc2[i][j] = fmaf(x2[i], w2[j], acc2[i][j]);
                }
        }
        __syncthreads();
    }
    #pragma unroll
    for (int i=0;i<4;i++){
        int j = j0 + (tr<<2) + i;
        if (j >= 384) continue;
        #pragma unroll
        for (int q=0;q<4;q++){
            int h = h0 + (tc<<2) + q;
            g_Wcat[(size_t)j*KX + h]       = acc1[i][q];
            g_Wcat[(size_t)j*KX + 128 + h] = acc2[i][q];
        }
    }
}

// ---------------- prep B: Wcat cols [256:384) = w_hh, cols 384/385 = uin/uout, bias bc ----------------
__global__ void k_prep_wcat2(const float* __restrict__ w_ih, const float* __restrict__ w_hh,
                             const float* __restrict__ b_ih, const float* __restrict__ b_hh,
                             const float* __restrict__ b_ein, const float* __restrict__ b_eout,
                             const float* __restrict__ b_iah, const float* __restrict__ b_oah){
    int j = blockIdx.x, h = threadIdx.x;
    int jrow = (j < 384) ? j : 256 + (j - 384);
    g_Wcat[(size_t)j*KX + 256 + h] = w_hh[(size_t)jrow*H_ + h];
    __shared__ float4 red[128];
    float4 v = make_float4(0.f,0.f,0.f,0.f);
    if (j < 384){
        float p1 = w_ih[(size_t)j*256 + h];
        float p2 = w_ih[(size_t)j*256 + 128 + h];
        v = make_float4(p1*b_ein[h], p2*b_eout[h], p1*b_iah[h], p2*b_oah[h]);
    }
    red[h] = v;
    for (int s = 64; s; s >>= 1){
        __syncthreads();
        if (h < s){
            float4 o = red[h+s];
            red[h].x += o.x; red[h].y += o.y; red[h].z += o.z; red[h].w += o.w;
        }
    }
    __syncthreads();
    if (h == 0){
        float4 t = red[0];
        g_Wcat[(size_t)j*KX + 384] = (j < 384) ? t.x : 0.f;
        g_Wcat[(size_t)j*KX + 385] = (j < 384) ? t.y : 0.f;
        g_bc[j] = (j < 384) ? (b_ih[j] + b_hh[j] + t.z + t.w) : b_hh[jrow];
    }
    if (h < 14) g_Wcat[(size_t)j*KX + 386 + h] = 0.f;
}

// ---------------- gather + rowsums + Xcat init ----------------
__global__ void k_gather(const int* __restrict__ items, const float* __restrict__ emb,
                         const float* __restrict__ A){
    int r = blockIdx.x, tid = threadIdx.x;
    float v = emb[(size_t)items[r]*H_ + tid];
    g_hidden[r*H_ + tid] = v;
    g_Xcat[(size_t)r*KX + 256 + tid] = v;
    int lane = tid & 31, wid = tid >> 5;
    if (wid < 2){
        float s = 0.f;
        for (int m = lane; m < N_; m += 32) s += A[(size_t)r*2*N_ + wid*N_ + m];
        for (int d = 16; d; d >>= 1) s += __shfl_xor_sync(0xffffffffu, s, d);
        if (lane == 0) g_Xcat[(size_t)r*KX + 384 + wid] = s;
    }
    if (tid >= 64 && tid < 78) g_Xcat[(size_t)r*KX + 386 + (tid - 64)] = 0.f;
}

// ---------------- prop2: AHin/AHout = A @ hidden -> Xcat[:,0:256) ----------------
__global__ void k_prop2(const float* __restrict__ A){
    int r = blockIdx.x;
    int b = r / N_;
    int h = threadIdx.x;
    __shared__ float arow[2*N_];
    if (h < 2*N_) arow[h] = A[(size_t)r*2*N_ + h];
    __syncthreads();
    float sin = 0.f, sout = 0.f;
    #pragma unroll 10
    for (int m = 0; m < N_; m++){
        sin  = fmaf(arow[m],     g_hidden[(b*N_+m)*H_ + h], sin);
        sout = fmaf(arow[N_+m],  g_hidden[(b*N_+m)*H_ + h], sout);
    }
    g_Xcat[(size_t)r*KX + h]       = sin;
    g_Xcat[(size_t)r*KX + 128 + h] = sout;
}

// ---------------- GRU gate from T; updates hidden + Xcat hidden slot ----------------
__global__ void k_gate2(){
    int r = blockIdx.x, h = threadIdx.x;
    float sr  = g_T[(size_t)r*512 + h];
    float si  = g_T[(size_t)r*512 + 128 + h];
    float sn  = g_T[(size_t)r*512 + 256 + h];
    float hnv = g_T[(size_t)r*512 + 384 + h];
    float rg = sigmoidf_(sr);
    float ig = sigmoidf_(si);
    float ng = tanhf(sn - hnv + rg * hnv);
    float hv = g_hidden[(size_t)r*H_ + h];
    float nh = ng + ig * (hv - ng);
    g_hidden[(size_t)r*H_ + h] = nh;
    g_Xcat[(size_t)r*KX + 256 + h] = nh;
}

// ---------------- fused attention head: len, ht, q1, alpha, cat, a ----------------
__global__ void k_alpha2(const int* __restrict__ mask, const float* __restrict__ w3,
                         const float* __restrict__ W_one, const float* __restrict__ b_one,
                         const float* __restrict__ W_tr,  const float* __restrict__ b_tr){
    int b = blockIdx.x, tid = threadIdx.x;
    __shared__ int slen;
    __shared__ float hts[128], q1s[128], logits[N_], cats[256];
    int warp = tid >> 5, lane = tid & 31;
    if (tid == 0){
        int s = 0;
        for (int n = 0; n < N_; n++) s += mask[b*N_+n];
        slen = s;
        g_len[b] = s;
    }
    __syncthreads();
    const int len = slen;
    float htv = g_hidden[(size_t)(b*N_ + len - 1)*H_ + tid];
    hts[tid] = htv;
    __syncthreads();
    float q1 = b_one[tid];
    #pragma unroll 8
    for (int k = 0; k < H_; k++) q1 = fmaf(hts[k], W_one[(size_t)tid*H_ + k], q1);
    q1s[tid] = q1;
    __syncthreads();
    for (int n = warp; n < len; n += 4){
        float s = 0.f;
        for (int hh = lane; hh < H_; hh += 32){
            float x = q1s[hh] + g_q2qt[(size_t)(b*N_+n)*256 + hh];
            s += sigmoidf_(x) * w3[hh];
        }
        for (int d = 16; d; d >>= 1) s += __shfl_xor_sync(0xffffffffu, s, d);
        if (lane == 0) logits[n] = s;
    }
    __syncthreads();
    float mx = -3.0e38f;
    for (int n = 0; n < len; n++) mx = fmaxf(mx, logits[n]);
    float denom = 0.f;
    for (int n = 0; n < len; n++) denom += expf(logits[n]-mx);
    float s = 0.f;
    for (int n = 0; n < len; n++)
        s = fmaf(expf(logits[n]-mx), g_hidden[(size_t)(b*N_+n)*H_ + tid], s);
    cats[tid] = s / denom;
    cats[128 + tid] = htv;
    __syncthreads();
    float av = b_tr[tid];
    #pragma unroll 8
    for (int k = 0; k < 256; k++) av = fmaf(cats[k], W_tr[(size_t)tid*256 + k], av);
    g_a[b*H_ + tid] = av;
}

// ---------------- prep: emb -> bf16 hi/lo tiles, coalesced (warp = chunks x rows) ----------------
__global__ void k_prep_emb(const float* __restrict__ emb){
    int t = blockIdx.x;
    int c  = threadIdx.x & 15;       // chunk 0..15
    int r8 = threadIdx.x >> 4;       // 0..15
    uint4* dh = reinterpret_cast<uint4*>(g_embh);
    uint4* dl = reinterpret_cast<uint4*>(g_embl);
    #pragma unroll
    for (int it = 0; it < 8; it++){
        int r = r8 + (it << 4);      // 0..127
        int vg = t*128 + r;
        bool ok = vg < VM1;
        const float4* src = reinterpret_cast<const float4*>(emb + (size_t)(vg+1)*H_);
        float4 f0 = ok ? src[2*c]   : make_float4(0.f,0.f,0.f,0.f);
        float4 f1 = ok ? src[2*c+1] : make_float4(0.f,0.f,0.f,0.f);
        uint4 hi, lo;
        hi.x = bf16pair(f0.x, f0.y); hi.y = bf16pair(f0.z, f0.w);
        hi.z = bf16pair(f1.x, f1.y); hi.w = bf16pair(f1.z, f1.w);
        lo.x = bf16pair(f0.x - bf16of(f0.x), f0.y - bf16of(f0.y));
        lo.y = bf16pair(f0.z - bf16of(f0.z), f0.w - bf16of(f0.w));
        lo.z = bf16pair(f1.x - bf16of(f1.x), f1.y - bf16of(f1.y));
        lo.w = bf16pair(f1.z - bf16of(f1.z), f1.w - bf16of(f1.w));
        size_t o = ((size_t)t*128 + r)*16 + (c ^ (r & 7));
        dh[o] = hi;
        dl[o] = lo;
    }
}

// ---------------- pack qt/a -> per-batch B tiles; a at column len ----------------
__global__ void k_pack_tc(const float* __restrict__ a){
    int b = blockIdx.x, n = threadIdx.x;   // 64 threads
    int len = g_len[b];
    const float* src = (n < len) ? (g_q2qt + (size_t)(b*N_+n)*256 + 128)
                 : (n == len)    ? (a + (size_t)b*H_) : nullptr;
    uint4* dh = reinterpret_cast<uint4*>(g_qbh);
    uint4* dl = reinterpret_cast<uint4*>(g_qbl);
    size_t rb = ((size_t)b*64 + n)*16;
    #pragma unroll
    for (int c = 0; c < 16; c++){
        float4 f0 = src ? *reinterpret_cast<const float4*>(src + c*8)     : make_float4(0.f,0.f,0.f,0.f);
        float4 f1 = src ? *reinterpret_cast<const float4*>(src + c*8 + 4) : make_float4(0.f,0.f,0.f,0.f);
        uint4 hi, lo;
        hi.x = bf16pair(f0.x, f0.y); hi.y = bf16pair(f0.z, f0.w);
        hi.z = bf16pair(f1.x, f1.y); hi.w = bf16pair(f1.z, f1.w);
        lo.x = bf16pair(f0.x - bf16of(f0.x), f0.y - bf16of(f0.y));
        lo.y = bf16pair(f0.z - bf16of(f0.z), f0.w - bf16of(f0.w));
        lo.z = bf16pair(f1.x - bf16of(f1.x), f1.y - bf16of(f1.y));
        lo.w = bf16pair(f1.z - bf16of(f1.z), f1.w - bf16of(f1.w));
        size_t o = rb + (c ^ (n & 7));
        dh[o] = hi;
        dl[o] = lo;
    }
}

// ---------------- HMMA vocab scoring ----------------
// Mainloop: outer ni2 with ONE uniform len-guard each; inner ks branchless (R14 WIN).
// Epilogue: fully branchless — selects + exp-underflow masking, no BSSY regions.
#define SC_AH 0
#define SC_AL 32768
#define SC_BH 65536
#define SC_BL 81920
#define SC_BYTES 98304

__global__ void __launch_bounds__(256, 2)
k_scores_mma(float* __restrict__ out){
    extern __shared__ char sm[];
    unsigned sbase = smem_u32(sm);
    const int tid = threadIdx.x, wid = tid >> 5, lane = tid & 31;
    const int t = blockIdx.x;

    // stage A tiles (pre-swizzled): 32KB hi + 32KB lo
    {
        const uint4* sh = reinterpret_cast<const uint4*>(g_embh + (size_t)t*32768);
        const uint4* sl = reinterpret_cast<const uint4*>(g_embl + (size_t)t*32768);
        uint4* dh = reinterpret_cast<uint4*>(sm + SC_AH);
        uint4* dl = reinterpret_cast<uint4*>(sm + SC_AL);
        #pragma unroll
        for (int i = 0; i < 8; i++){
            dh[tid + (i<<8)] = sh[tid + (i<<8)];
            dl[tid + (i<<8)] = sl[tid + (i<<8)];
        }
    }

    const int r0   = wid << 4;
    const int rowA = r0 + (lane & 15);
    const int phA  = rowA & 7;
    const int hl   = lane >> 4;
    const unsigned baseAh = sbase + SC_AH + rowA*256;
    const unsigned baseAl = sbase + SC_AL + rowA*256;
    const int rowB = (lane & 15);
    const int phB0 = rowB & 7;

    for (int b = 0; b < B_; b++){
        __syncthreads();
        // stage B tiles (16KB hi + 16KB lo)
        {
            const uint4* sh = reinterpret_cast<const uint4*>(g_qbh + (size_t)b*16384);
            const uint4* sl = reinterpret_cast<const uint4*>(g_qbl + (size_t)b*16384);
            uint4* dh = reinterpret_cast<uint4*>(sm + SC_BH);
            uint4* dl = reinterpret_cast<uint4*>(sm + SC_BL);
            #pragma unroll
            for (int i = 0; i < 4; i++){
                dh[tid + (i<<8)] = sh[tid + (i<<8)];
                dl[tid + (i<<8)] = sl[tid + (i<<8)];
            }
        }
        __syncthreads();
        const int len = g_len[b];

        float acc[8][4];
        #pragma unroll
        for (int ni = 0; ni < 8; ni++)
            #pragma unroll
            for (int e = 0; e < 4; e++) acc[ni][e] = 0.f;

        // outer ni2: one uniform guard per 16-column pair; inner ks branchless
        #pragma unroll
        for (int ni2 = 0; ni2 < 4; ni2++){
            if (ni2*16 <= len){
                #pragma unroll
                for (int ks = 0; ks < 8; ks++){
                    unsigned offA = (unsigned)(((ks*2 + hl) ^ phA) << 4);
                    unsigned ah0,ah1,ah2,ah3, al0,al1,al2,al3;
                    ldsm4(ah0, ah1, ah2, ah3, baseAh + offA);
                    ldsm4(al0, al1, al2, al3, baseAl + offA);
                    unsigned offB = (unsigned)((ni2*16 + rowB)*256 + (((ks*2 + hl) ^ phB0) << 4));
                    unsigned q0,q1,q2,q3, p0,p1,p2,p3;
                    ldsm4(q0,q1,q2,q3, sbase + SC_BH + offB);
                    ldsm4(p0,p1,p2,p3, sbase + SC_BL + offB);
                    mma16816(acc[2*ni2],   ah0,ah1,ah2,ah3, q0, q2);
                    mma16816(acc[2*ni2],   ah0,ah1,ah2,ah3, p0, p2);
                    mma16816(acc[2*ni2],   al0,al1,al2,al3, q0, q2);
                    mma16816(acc[2*ni2+1], ah0,ah1,ah2,ah3, q1, q3);
                    mma16816(acc[2*ni2+1], ah0,ah1,ah2,ah3, p1, p3);
                    mma16816(acc[2*ni2+1], al0,al1,al2,al3, q1, q3);
                }
            }
        }

        // ---- branchless epilogue ----
        // a-dot extraction via selects (column len: tile len>>3, in-tile col len&7)
        const int t8 = len >> 3, l1 = len & 1;
        float av0 = 0.f, av8 = 0.f;
        #pragma unroll
        for (int ni = 0; ni < 8; ni++){
            bool sel = (ni == t8);
            float c0 = l1 ? acc[ni][1] : acc[ni][0];
            float c8 = l1 ? acc[ni][3] : acc[ni][2];
            av0 = sel ? c0 : av0;
            av8 = sel ? c8 : av8;
        }
        const int alane = (lane & ~3) | ((len & 7) >> 1);
        float ad0 = __shfl_sync(0xffffffffu, av0, alane);
        float ad8 = __shfl_sync(0xffffffffu, av8, alane);

        const int cb = (lane & 3) << 1;
        #pragma unroll
        for (int rh = 0; rh < 2; rh++){
            float mx = -3.0e38f;
            #pragma unroll
            for (int ni = 0; ni < 8; ni++){
                #pragma unroll
                for (int e = 0; e < 2; e++){
                    int n = ni*8 + cb + e;
                    float f = acc[ni][rh*2+e];
                    mx = fmaxf(mx, (n < len) ? f : -3.0e38f);
                }
            }
            mx = fmaxf(mx, __shfl_xor_sync(0xffffffffu, mx, 1));
            mx = fmaxf(mx, __shfl_xor_sync(0xffffffffu, mx, 2));
            float se = 0.f, sw = 0.f;
            #pragma unroll
            for (int ni = 0; ni < 8; ni++){
                #pragma unroll
                for (int e = 0; e < 2; e++){
                    int n = ni*8 + cb + e;
                    float f = acc[ni][rh*2+e];
                    float fv = (n < len) ? f : -3.0e38f;
                    float ex = __expf(fv - mx);     // exactly 0 for invalid n
                    se += ex;
                    sw = fmaf(ex, f, sw);           // acc is 0-init, f always finite
                }
            }
            se += __shfl_xor_sync(0xffffffffu, se, 1);
            sw += __shfl_xor_sync(0xffffffffu, sw, 1);
            se += __shfl_xor_sync(0xffffffffu, se, 2);
            sw += __shfl_xor_sync(0xffffffffu, sw, 2);
            if ((lane & 3) == 0){
                int v = t*128 + r0 + (lane >> 2) + rh*8;
                if (v < VM1) out[(size_t)b*VM1 + v] = sw/se + (rh ? ad8 : ad0);
            }
        }
    }
}

// ---------------- host side ----------------
static float* symaddr(const void* sym){
    void* p = nullptr;
    cudaGetSymbolAddress(&p, sym);
    return (float*)p;
}

extern "C" void kernel_launch(void* const* d_in, const int* in_sizes, int n_in,
                              void* d_out, int out_size){
    (void)in_sizes; (void)n_in; (void)out_size;
    const int*   items  = (const int*)  d_in[0];
    const float* A      = (const float*)d_in[1];
    const int*   mask   = (const int*)  d_in[2];
    const float* emb    = (const float*)d_in[3];
    const float* w_ih   = (const float*)d_in[4];
    const float* w_hh   = (const float*)d_in[5];
    const float* b_ih   = (const float*)d_in[6];
    const float* b_hh   = (const float*)d_in[7];
    const float* b_iah  = (const float*)d_in[8];
    const float* b_oah  = (const float*)d_in[9];
    const float* W_ein  = (const float*)d_in[10];
    const float* b_ein  = (const float*)d_in[11];
    const float* W_eout = (const float*)d_in[12];
    const float* b_eout = (const float*)d_in[13];
    const float* W_one  = (const float*)d_in[14];
    const float* b_one  = (const float*)d_in[15];
    const float* W_two  = (const float*)d_in[16];
    const float* b_two  = (const float*)d_in[17];
    const float* w_three= (const float*)d_in[18];
    const float* W_tr   = (const float*)d_in[19];
    const float* b_tr   = (const float*)d_in[20];
    const float* W_t    = (const float*)d_in[21];
    float* out = (float*)d_out;

    float* Xcat = symaddr(g_Xcat);
    float* Wcat = symaddr(g_Wcat);
    float* bc   = symaddr(g_bc);
    float* T    = symaddr(g_T);
    float* hid  = symaddr(g_hidden);
    float* q2qt = symaddr(g_q2qt);
    float* a    = symaddr(g_a);

    static int init_done = 0;
    if (!init_done){
        cudaFuncSetAttribute(k_scores_mma, cudaFuncAttributeMaxDynamicSharedMemorySize, SC_BYTES);
        init_done = 1;
    }

    // one-time preps (serial, single stream — measured fastest)
    {
        dim3 g(2, 6);
        k_prep_wa<<<g, 256>>>(w_ih, W_ein, W_eout);
    }
    k_prep_wcat2<<<512, 128>>>(w_ih, w_hh, b_ih, b_hh, b_ein, b_eout, b_iah, b_oah);
    k_prep_emb<<<NT_, 256>>>(emb);
    k_gather<<<R_, H_>>>(items, emb, A);

    // 2 GNN steps: prop2 -> fast combined GEMM -> gate
    for (int step = 0; step < 2; step++){
        k_prop2<<<R_, H_>>>(A);
        dim3 gt(8, 7);
        k_gemm_f<<<gt, 256>>>(Xcat, Wcat, Wcat, 512, bc, nullptr, T, R_, KX, 512);
        k_gate2<<<R_, H_>>>();
    }

    // attention head: one GEMM produces [q2 | qt]
    {
        dim3 gq(4, 7);
        k_gemm_f<<<gq, 256>>>(hid, W_two, W_t, 128, b_two, nullptr, q2qt, R_, H_, 256);
    }
    k_alpha2<<<B_, H_>>>(mask, w_three, W_one, b_one, W_tr, b_tr);
    k_pack_tc<<<B_, 64>>>(a);

    // HMMA vocab scoring
    k_scores_mma<<<NT_, 256, SC_BYTES>>>(out);
}

// round 17
// speedup vs baseline: 1.6327x; 1.0667x over previous
#include <cuda_runtime.h>
#include <cuda_bf16.h>
#include <math.h>

// Problem constants
#define B_  16
#define N_  50
#define H_  128
#define V_  40000
#define VM1 39999      // V-1 rows of b_emb / output columns
#define R_  (B_*N_)    // 800 rows
#define NT_ 313        // ceil(VM1/128) vocab tiles (128 rows each)
#define KX  400        // padded Xcat/Wcat K (386 used)

// ---------------- scratch (static __device__, no allocs) ----------------
__device__ float g_hidden[R_*H_];
__device__ float g_Xcat  [R_*KX];      // [AHin(128) | AHout(128) | hidden(128) | rsin | rsout | pad]
__device__ float g_Wcat  [512*KX];     // rows interleaved: jn = h*4 + g, g in {r,i,n,hn}
__device__ float g_bc    [512];
__device__ float g_q2qt  [R_*256];     // cols 0..127 = q2, cols 128..255 = qt
// HMMA staging: bf16 hi/lo split, ldmatrix XOR-chunk swizzled layouts
__device__ unsigned char g_embh[(size_t)NT_*32768];
__device__ unsigned char g_embl[(size_t)NT_*32768];
__device__ unsigned char g_qbh [B_*16384];
__device__ unsigned char g_qbl [B_*16384];
__device__ int g_len[B_];

// ---------------- small helpers ----------------
__device__ __forceinline__ float sigmoidf_(float x){ return 1.f/(1.f+expf(-x)); }

__device__ __forceinline__ unsigned smem_u32(const void* p){
    unsigned a;
    asm("{ .reg .u64 t; cvta.to.shared.u64 t, %1; cvt.u32.u64 %0, t; }" : "=r"(a) : "l"(p));
    return a;
}
__device__ __forceinline__ unsigned long long pack2(float x, float y){
    unsigned long long r;
    asm("mov.b64 %0, {%1, %2};" : "=l"(r) : "f"(x), "f"(y));
    return r;
}
__device__ __forceinline__ unsigned long long fma2(unsigned long long a,
                                                   unsigned long long b,
                                                   unsigned long long c){
    unsigned long long d;
    asm("fma.rn.f32x2 %0, %1, %2, %3;" : "=l"(d) : "l"(a), "l"(b), "l"(c));
    return d;
}
__device__ __forceinline__ float lo2(unsigned long long u){
    return __uint_as_float((unsigned)(u & 0xffffffffULL));
}
__device__ __forceinline__ float hi2(unsigned long long u){
    return __uint_as_float((unsigned)(u >> 32));
}
__device__ __forceinline__ unsigned bf16pair(float a, float b){
    __nv_bfloat162 t = __floats2bfloat162_rn(a, b);
    return *reinterpret_cast<unsigned*>(&t);
}
__device__ __forceinline__ float bf16of(float x){
    return __bfloat162float(__float2bfloat16(x));
}
__device__ __forceinline__ void ldsm4(unsigned& r0, unsigned& r1, unsigned& r2, unsigned& r3,
                                      unsigned addr){
    asm volatile("ldmatrix.sync.aligned.m8n8.x4.shared.b16 {%0,%1,%2,%3}, [%4];"
                 : "=r"(r0),"=r"(r1),"=r"(r2),"=r"(r3) : "r"(addr));
}
__device__ __forceinline__ void mma16816(float* c, unsigned a0, unsigned a1, unsigned a2,
                                         unsigned a3, unsigned b0, unsigned b1){
    asm volatile(
        "mma.sync.aligned.m16n8k16.row.col.f32.bf16.bf16.f32 "
        "{%0,%1,%2,%3}, {%4,%5,%6,%7}, {%8,%9}, {%0,%1,%2,%3};"
        : "+f"(c[0]), "+f"(c[1]), "+f"(c[2]), "+f"(c[3])
        : "r"(a0), "r"(a1), "r"(a2), "r"(a3), "r"(b0), "r"(b1));
}

// ---------------- fast SGEMM: 128x64 tile, 256 threads, 8r x 4j per thread ----------------
// gate_mode=0: out[r,j] = sum_k X[r,k]*W[j,k] + bias. W row j from W0 (j<Jsplit) or W1.
// gate_mode=1: (GNN) thread's 4 consecutive j = 4 gate pre-acts of h=(j0>>2)+tc;
//              applies GRU gate inline and writes g_hidden[r,h]. out unused.
__global__ void __launch_bounds__(256)
k_gemm_f(const float* __restrict__ X, const float* __restrict__ W0,
         const float* __restrict__ W1, int Jsplit,
         const float* __restrict__ bias0, const float* __restrict__ bias1,
         float* __restrict__ out, int R, int K, int J, int gate_mode){
    __shared__ __align__(16) float xs[16][132];
    __shared__ __align__(16) float ws[16][68];
    const int tid = threadIdx.x;
    const int tr = tid >> 4, tc = tid & 15;
    const int r0 = blockIdx.y << 7, j0 = blockIdx.x << 6;
    unsigned long long acc[4][4];
    #pragma unroll
    for (int p=0;p<4;p++)
        #pragma unroll
        for (int j=0;j<4;j++) acc[p][j] = 0ULL;

    for (int kc = 0; kc < K; kc += 16){
        // stage X chunk: 128 rows x 16 k (512 float4 loads)
        #pragma unroll
        for (int it = 0; it < 2; it++){
            int idx = tid + (it<<8);
            int rr = idx >> 2, kq = idx & 3;
            float4 v = make_float4(0.f,0.f,0.f,0.f);
            if (r0 + rr < R)
                v = *reinterpret_cast<const float4*>(X + (size_t)(r0+rr)*K + kc + (kq<<2));
            xs[(kq<<2)+0][rr] = v.x;
            xs[(kq<<2)+1][rr] = v.y;
            xs[(kq<<2)+2][rr] = v.z;
            xs[(kq<<2)+3][rr] = v.w;
        }
        // stage W chunk: 64 j x 16 k (256 float4 loads)
        {
            int jj = tid >> 2, kq = tid & 3;
            int j = j0 + jj;
            float4 v = make_float4(0.f,0.f,0.f,0.f);
            if (j < J){
                const float* Wr = (j < Jsplit) ? (W0 + (size_t)j*K)
                                               : (W1 + (size_t)(j-Jsplit)*K);
                v = *reinterpret_cast<const float4*>(Wr + kc + (kq<<2));
            }
            ws[(kq<<2)+0][jj] = v.x;
            ws[(kq<<2)+1][jj] = v.y;
            ws[(kq<<2)+2][jj] = v.z;
            ws[(kq<<2)+3][jj] = v.w;
        }
        __syncthreads();
        #pragma unroll
        for (int kk = 0; kk < 16; kk++){
            float4 xA = *reinterpret_cast<const float4*>(&xs[kk][tr<<3]);
            float4 xB = *reinterpret_cast<const float4*>(&xs[kk][(tr<<3)+4]);
            float4 wv = *reinterpret_cast<const float4*>(&ws[kk][tc<<2]);
            unsigned long long xu0 = pack2(xA.x, xA.y);
            unsigned long long xu1 = pack2(xA.z, xA.w);
            unsigned long long xu2 = pack2(xB.x, xB.y);
            unsigned long long xu3 = pack2(xB.z, xB.w);
            float wf[4] = {wv.x, wv.y, wv.z, wv.w};
            #pragma unroll
            for (int j = 0; j < 4; j++){
                unsigned long long wb = pack2(wf[j], wf[j]);
                acc[0][j] = fma2(xu0, wb, acc[0][j]);
                acc[1][j] = fma2(xu1, wb, acc[1][j]);
                acc[2][j] = fma2(xu2, wb, acc[2][j]);
                acc[3][j] = fma2(xu3, wb, acc[3][j]);
            }
        }
        __syncthreads();
    }

    if (gate_mode){
        // thread's 4 j = gates {r,i,n,hn} of h
        const int h = (j0 >> 2) + tc;
        float b0v = bias0[j0 + (tc<<2) + 0];
        float b1v = bias0[j0 + (tc<<2) + 1];
        float b2v = bias0[j0 + (tc<<2) + 2];
        float b3v = bias0[j0 + (tc<<2) + 3];
        #pragma unroll
        for (int p = 0; p < 4; p++){
            #pragma unroll
            for (int e = 0; e < 2; e++){
                int r = r0 + (tr<<3) + (p<<1) + e;
                if (r >= R) continue;
                float sr  = (e ? hi2(acc[p][0]) : lo2(acc[p][0])) + b0v;
                float si  = (e ? hi2(acc[p][1]) : lo2(acc[p][1])) + b1v;
                float sn  = (e ? hi2(acc[p][2]) : lo2(acc[p][2])) + b2v;
                float hnv = (e ? hi2(acc[p][3]) : lo2(acc[p][3])) + b3v;
                float rg = sigmoidf_(sr);
                float ig = sigmoidf_(si);
                float ng = tanhf(sn - hnv + rg * hnv);
                float hv = g_hidden[(size_t)r*H_ + h];
                g_hidden[(size_t)r*H_ + h] = ng + ig * (hv - ng);
            }
        }
        return;
    }

    #pragma unroll
    for (int p = 0; p < 4; p++){
        #pragma unroll
        for (int e = 0; e < 2; e++){
            int r = r0 + (tr<<3) + (p<<1) + e;
            if (r >= R) continue;
            #pragma unroll
            for (int j = 0; j < 4; j++){
                int jj = j0 + (tc<<2) + j;
                if (jj >= J) continue;
                float bv = (jj < Jsplit) ? (bias0 ? bias0[jj] : 0.f)
                                         : (bias1 ? bias1[jj - Jsplit] : 0.f);
                float val = e ? hi2(acc[p][j]) : lo2(acc[p][j]);
                out[(size_t)r*J + jj] = val + bv;
            }
        }
    }
}

// ---------------- prep A: WA/WB = w_ih halves @ W_ein/W_eout -> Wcat (interleaved rows) ----------------
__global__ void k_prep_wa(const float* __restrict__ w_ih, const float* __restrict__ W_ein,
                          const float* __restrict__ W_eout){
    __shared__ float xs1[16][65], xs2[16][65];
    __shared__ float ws1[16][65], ws2[16][65];
    int tid = threadIdx.x;
    int tr = tid >> 4, tc = tid & 15;
    int j0 = blockIdx.y << 6, h0 = blockIdx.x << 6;
    float acc1[4][4] = {}, acc2[4][4] = {};
    for (int kc = 0; kc < H_; kc += 16){
        for (int t = tid; t < 1024; t += 256){
            int rr = t >> 4, kk = t & 15;
            int j = j0 + rr;
            xs1[kk][rr] = (j < 384) ? w_ih[(size_t)j*256 + kc + kk]       : 0.f;
            xs2[kk][rr] = (j < 384) ? w_ih[(size_t)j*256 + 128 + kc + kk] : 0.f;
        }
        for (int t = tid; t < 1024; t += 256){
            int jj = t >> 4, kk = t & 15;
            ws1[kk][jj] = W_ein [(size_t)(kc+kk)*H_ + h0 + jj];
            ws2[kk][jj] = W_eout[(size_t)(kc+kk)*H_ + h0 + jj];
        }
        __syncthreads();
        #pragma unroll
        for (int kk = 0; kk < 16; kk++){
            float x1[4], x2[4], w1[4], w2[4];
            #pragma unroll
            for (int i=0;i<4;i++){ x1[i]=xs1[kk][(tr<<2)+i]; x2[i]=xs2[kk][(tr<<2)+i]; }
            #pragma unroll
            for (int j=0;j<4;j++){ w1[j]=ws1[kk][(tc<<2)+j]; w2[j]=ws2[kk][(tc<<2)+j]; }
            #pragma unroll
            for (int i=0;i<4;i++)
                #pragma unroll
                for (int j=0;j<4;j++){
                    acc1[i][j] = fmaf(x1[i], w1[j], acc1[i][j]);
                    acc2[i][j] = fmaf(x2[i], w2[j], acc2[i][j]);
                }
        }
        __syncthreads();
    }
    #pragma unroll
    for (int i=0;i<4;i++){
        int j = j0 + (tr<<2) + i;
        if (j >= 384) continue;
        int jn = (j & 127)*4 + (j >> 7);      // interleaved row
        #pragma unroll
        for (int q=0;q<4;q++){
            int h = h0 + (tc<<2) + q;
            g_Wcat[(size_t)jn*KX + h]       = acc1[i][q];
            g_Wcat[(size_t)jn*KX + 128 + h] = acc2[i][q];
        }
    }
}

// ---------------- prep B: Wcat cols [256:384) = w_hh, cols 384/385 = uin/uout, bias bc ----------------
__global__ void k_prep_wcat2(const float* __restrict__ w_ih, const float* __restrict__ w_hh,
                             const float* __restrict__ b_ih, const float* __restrict__ b_hh,
                             const float* __restrict__ b_ein, const float* __restrict__ b_eout,
                             const float* __restrict__ b_iah, const float* __restrict__ b_oah){
    int j = blockIdx.x, h = threadIdx.x;
    int jrow = (j < 384) ? j : 256 + (j - 384);
    int jn   = (j < 384) ? ((j & 127)*4 + (j >> 7)) : ((j - 384)*4 + 3);
    g_Wcat[(size_t)jn*KX + 256 + h] = w_hh[(size_t)jrow*H_ + h];
    __shared__ float4 red[128];
    float4 v = make_float4(0.f,0.f,0.f,0.f);
    if (j < 384){
        float p1 = w_ih[(size_t)j*256 + h];
        float p2 = w_ih[(size_t)j*256 + 128 + h];
        v = make_float4(p1*b_ein[h], p2*b_eout[h], p1*b_iah[h], p2*b_oah[h]);
    }
    red[h] = v;
    for (int s = 64; s; s >>= 1){
        __syncthreads();
        if (h < s){
            float4 o = red[h+s];
            red[h].x += o.x; red[h].y += o.y; red[h].z += o.z; red[h].w += o.w;
        }
    }
    __syncthreads();
    if (h == 0){
        float4 t = red[0];
        g_Wcat[(size_t)jn*KX + 384] = (j < 384) ? t.x : 0.f;
        g_Wcat[(size_t)jn*KX + 385] = (j < 384) ? t.y : 0.f;
        g_bc[jn] = (j < 384) ? (b_ih[j] + b_hh[j] + t.z + t.w) : b_hh[jrow];
    }
    if (h < 14) g_Wcat[(size_t)jn*KX + 386 + h] = 0.f;
}

// ---------------- gather + rowsums + Xcat init ----------------
__global__ void k_gather(const int* __restrict__ items, const float* __restrict__ emb,
                         const float* __restrict__ A){
    int r = blockIdx.x, tid = threadIdx.x;
    float v = emb[(size_t)items[r]*H_ + tid];
    g_hidden[r*H_ + tid] = v;
    g_Xcat[(size_t)r*KX + 256 + tid] = v;
    int lane = tid & 31, wid = tid >> 5;
    if (wid < 2){
        float s = 0.f;
        for (int m = lane; m < N_; m += 32) s += A[(size_t)r*2*N_ + wid*N_ + m];
        for (int d = 16; d; d >>= 1) s += __shfl_xor_sync(0xffffffffu, s, d);
        if (lane == 0) g_Xcat[(size_t)r*KX + 384 + wid] = s;
    }
    if (tid >= 64 && tid < 78) g_Xcat[(size_t)r*KX + 386 + (tid - 64)] = 0.f;
}

// ---------------- prop2: AHin/AHout = A @ hidden -> Xcat[:,0:256); refresh hidden slot ----------------
__global__ void k_prop2(const float* __restrict__ A){
    int r = blockIdx.x;
    int b = r / N_;
    int h = threadIdx.x;
    __shared__ float arow[2*N_];
    if (h < 2*N_) arow[h] = A[(size_t)r*2*N_ + h];
    __syncthreads();
    float sin = 0.f, sout = 0.f;
    #pragma unroll 10
    for (int m = 0; m < N_; m++){
        sin  = fmaf(arow[m],     g_hidden[(b*N_+m)*H_ + h], sin);
        sout = fmaf(arow[N_+m],  g_hidden[(b*N_+m)*H_ + h], sout);
    }
    g_Xcat[(size_t)r*KX + h]       = sin;
    g_Xcat[(size_t)r*KX + 128 + h] = sout;
    g_Xcat[(size_t)r*KX + 256 + h] = g_hidden[(size_t)r*H_ + h];  // gate-fused GEMM updated hidden only
}

// ---------------- fused attention head: len, ht, q1, alpha, cat, a, B-tile pack ----------------
__global__ void k_alpha2(const int* __restrict__ mask, const float* __restrict__ w3,
                         const float* __restrict__ W_one, const float* __restrict__ b_one,
                         const float* __restrict__ W_tr,  const float* __restrict__ b_tr){
    int b = blockIdx.x, tid = threadIdx.x;
    __shared__ int slen;
    // av_s is read via float4 in the fused pack: keep it first and 16B-aligned.
    __shared__ __align__(16) float av_s[128];
    __shared__ __align__(16) float hts[128];
    __shared__ __align__(16) float q1s[128];
    __shared__ __align__(16) float cats[256];
    __shared__ __align__(16) float logits[N_ + 2];
    int warp = tid >> 5, lane = tid & 31;
    if (tid == 0){
        int s = 0;
        for (int n = 0; n < N_; n++) s += mask[b*N_+n];
        slen = s;
        g_len[b] = s;
    }
    __syncthreads();
    const int len = slen;
    float htv = g_hidden[(size_t)(b*N_ + len - 1)*H_ + tid];
    hts[tid] = htv;
    __syncthreads();
    float q1 = b_one[tid];
    #pragma unroll 8
    for (int k = 0; k < H_; k++) q1 = fmaf(hts[k], W_one[(size_t)tid*H_ + k], q1);
    q1s[tid] = q1;
    __syncthreads();
    for (int n = warp; n < len; n += 4){
        float s = 0.f;
        for (int hh = lane; hh < H_; hh += 32){
            float x = q1s[hh] + g_q2qt[(size_t)(b*N_+n)*256 + hh];
            s += sigmoidf_(x) * w3[hh];
        }
        for (int d = 16; d; d >>= 1) s += __shfl_xor_sync(0xffffffffu, s, d);
        if (lane == 0) logits[n] = s;
    }
    __syncthreads();
    float mx = -3.0e38f;
    for (int n = 0; n < len; n++) mx = fmaxf(mx, logits[n]);
    float denom = 0.f;
    for (int n = 0; n < len; n++) denom += expf(logits[n]-mx);
    float s = 0.f;
    for (int n = 0; n < len; n++)
        s = fmaf(expf(logits[n]-mx), g_hidden[(size_t)(b*N_+n)*H_ + tid], s);
    cats[tid] = s / denom;
    cats[128 + tid] = htv;
    __syncthreads();
    float av = b_tr[tid];
    #pragma unroll 8
    for (int k = 0; k < 256; k++) av = fmaf(cats[k], W_tr[(size_t)tid*256 + k], av);
    av_s[tid] = av;
    __syncthreads();

    // ---- fused pack: qt rows (n<len) + a (n==len) -> bf16 hi/lo swizzled B tiles ----
    if (tid < 64){
        int n = tid;
        const float* src = (n < len) ? (g_q2qt + (size_t)(b*N_+n)*256 + 128)
                     : (n == len)    ? av_s : nullptr;
        uint4* dh = reinterpret_cast<uint4*>(g_qbh);
        uint4* dl = reinterpret_cast<uint4*>(g_qbl);
        size_t rb = ((size_t)b*64 + n)*16;
        #pragma unroll
        for (int c = 0; c < 16; c++){
            float4 f0 = src ? *reinterpret_cast<const float4*>(src + c*8)     : make_float4(0.f,0.f,0.f,0.f);
            float4 f1 = src ? *reinterpret_cast<const float4*>(src + c*8 + 4) : make_float4(0.f,0.f,0.f,0.f);
            uint4 hi, lo;
            hi.x = bf16pair(f0.x, f0.y); hi.y = bf16pair(f0.z, f0.w);
            hi.z = bf16pair(f1.x, f1.y); hi.w = bf16pair(f1.z, f1.w);
            lo.x = bf16pair(f0.x - bf16of(f0.x), f0.y - bf16of(f0.y));
            lo.y = bf16pair(f0.z - bf16of(f0.z), f0.w - bf16of(f0.w));
            lo.z = bf16pair(f1.x - bf16of(f1.x), f1.y - bf16of(f1.y));
            lo.w = bf16pair(f1.z - bf16of(f1.z), f1.w - bf16of(f1.w));
            size_t o = rb + (c ^ (n & 7));
            dh[o] = hi;
            dl[o] = lo;
        }
    }
}

// ---------------- prep: emb -> bf16 hi/lo tiles, coalesced (warp = chunks x rows) ----------------
__global__ void k_prep_emb(const float* __restrict__ emb){
    int t = blockIdx.x;
    int c  = threadIdx.x & 15;       // chunk 0..15
    int r8 = threadIdx.x >> 4;       // 0..15
    uint4* dh = reinterpret_cast<uint4*>(g_embh);
    uint4* dl = reinterpret_cast<uint4*>(g_embl);
    #pragma unroll
    for (int it = 0; it < 8; it++){
        int r = r8 + (it << 4);      // 0..127
        int vg = t*128 + r;
        bool ok = vg < VM1;
        const float4* src = reinterpret_cast<const float4*>(emb + (size_t)(vg+1)*H_);
        float4 f0 = ok ? src[2*c]   : make_float4(0.f,0.f,0.f,0.f);
        float4 f1 = ok ? src[2*c+1] : make_float4(0.f,0.f,0.f,0.f);
        uint4 hi, lo;
        hi.x = bf16pair(f0.x, f0.y); hi.y = bf16pair(f0.z, f0.w);
        hi.z = bf16pair(f1.x, f1.y); hi.w = bf16pair(f1.z, f1.w);
        lo.x = bf16pair(f0.x - bf16of(f0.x), f0.y - bf16of(f0.y));
        lo.y = bf16pair(f0.z - bf16of(f0.z), f0.w - bf16of(f0.w));
        lo.z = bf16pair(f1.x - bf16of(f1.x), f1.y - bf16of(f1.y));
        lo.w = bf16pair(f1.z - bf16of(f1.z), f1.w - bf16of(f1.w));
        size_t o = ((size_t)t*128 + r)*16 + (c ^ (r & 7));
        dh[o] = hi;
        dl[o] = lo;
    }
}

// ---------------- HMMA vocab scoring ----------------
// Mainloop: outer ni2 with ONE uniform len-guard each; inner ks branchless.
// Epilogue: fully branchless — selects + exp-underflow masking.
#define SC_AH 0
#define SC_AL 32768
#define SC_BH 65536
#define SC_BL 81920
#define SC_BYTES 98304

__global__ void __launch_bounds__(256, 2)
k_scores_mma(float* __restrict__ out){
    extern __shared__ char sm[];
    unsigned sbase = smem_u32(sm);
    const int tid = threadIdx.x, wid = tid >> 5, lane = tid & 31;
    const int t = blockIdx.x;

    // stage A tiles (pre-swizzled): 32KB hi + 32KB lo
    {
        const uint4* sh = reinterpret_cast<const uint4*>(g_embh + (size_t)t*32768);
        const uint4* sl = reinterpret_cast<const uint4*>(g_embl + (size_t)t*32768);
        uint4* dh = reinterpret_cast<uint4*>(sm + SC_AH);
        uint4* dl = reinterpret_cast<uint4*>(sm + SC_AL);
        #pragma unroll
        for (int i = 0; i < 8; i++){
            dh[tid + (i<<8)] = sh[tid + (i<<8)];
            dl[tid + (i<<8)] = sl[tid + (i<<8)];
        }
    }

    const int r0   = wid << 4;
    const int rowA = r0 + (lane & 15);
    const int phA  = rowA & 7;
    const int hl   = lane >> 4;
    const unsigned baseAh = sbase + SC_AH + rowA*256;
    const unsigned baseAl = sbase + SC_AL + rowA*256;
    const int rowB = (lane & 15);
    const int phB0 = rowB & 7;

    for (int b = 0; b < B_; b++){
        __syncthreads();
        // stage B tiles (16KB hi + 16KB lo)
        {
            const uint4* sh = reinterpret_cast<const uint4*>(g_qbh + (size_t)b*16384);
            const uint4* sl = reinterpret_cast<const uint4*>(g_qbl + (size_t)b*16384);
            uint4* dh = reinterpret_cast<uint4*>(sm + SC_BH);
            uint4* dl = reinterpret_cast<uint4*>(sm + SC_BL);
            #pragma unroll
            for (int i = 0; i < 4; i++){
                dh[tid + (i<<8)] = sh[tid + (i<<8)];
                dl[tid + (i<<8)] = sl[tid + (i<<8)];
            }
        }
        __syncthreads();
        const int len = g_len[b];

        float acc[8][4];
        #pragma unroll
        for (int ni = 0; ni < 8; ni++)
            #pragma unroll
            for (int e = 0; e < 4; e++) acc[ni][e] = 0.f;

        // outer ni2: one uniform guard per 16-column pair; inner ks branchless
        #pragma unroll
        for (int ni2 = 0; ni2 < 4; ni2++){
            if (ni2*16 <= len){
                #pragma unroll
                for (int ks = 0; ks < 8; ks++){
                    unsigned offA = (unsigned)(((ks*2 + hl) ^ phA) << 4);
                    unsigned ah0,ah1,ah2,ah3, al0,al1,al2,al3;
                    ldsm4(ah0, ah1, ah2, ah3, baseAh + offA);
                    ldsm4(al0, al1, al2, al3, baseAl + offA);
                    unsigned offB = (unsigned)((ni2*16 + rowB)*256 + (((ks*2 + hl) ^ phB0) << 4));
                    unsigned q0,q1,q2,q3, p0,p1,p2,p3;
                    ldsm4(q0,q1,q2,q3, sbase + SC_BH + offB);
                    ldsm4(p0,p1,p2,p3, sbase + SC_BL + offB);
                    mma16816(acc[2*ni2],   ah0,ah1,ah2,ah3, q0, q2);
                    mma16816(acc[2*ni2],   ah0,ah1,ah2,ah3, p0, p2);
                    mma16816(acc[2*ni2],   al0,al1,al2,al3, q0, q2);
                    mma16816(acc[2*ni2+1], ah0,ah1,ah2,ah3, q1, q3);
                    mma16816(acc[2*ni2+1], ah0,ah1,ah2,ah3, p1, p3);
                    mma16816(acc[2*ni2+1], al0,al1,al2,al3, q1, q3);
                }
            }
        }

        // ---- branchless epilogue ----
        const int t8 = len >> 3, l1 = len & 1;
        float av0 = 0.f, av8 = 0.f;
        #pragma unroll
        for (int ni = 0; ni < 8; ni++){
            bool sel = (ni == t8);
            float c0 = l1 ? acc[ni][1] : acc[ni][0];
            float c8 = l1 ? acc[ni][3] : acc[ni][2];
            av0 = sel ? c0 : av0;
            av8 = sel ? c8 : av8;
        }
        const int alane = (lane & ~3) | ((len & 7) >> 1);
        float ad0 = __shfl_sync(0xffffffffu, av0, alane);
        float ad8 = __shfl_sync(0xffffffffu, av8, alane);

        const int cb = (lane & 3) << 1;
        #pragma unroll
        for (int rh = 0; rh < 2; rh++){
            float mx = -3.0e38f;
            #pragma unroll
            for (int ni = 0; ni < 8; ni++){
                #pragma unroll
                for (int e = 0; e < 2; e++){
                    int n = ni*8 + cb + e;
                    float f = acc[ni][rh*2+e];
                    mx = fmaxf(mx, (n < len) ? f : -3.0e38f);
                }
            }
            mx = fmaxf(mx, __shfl_xor_sync(0xffffffffu, mx, 1));
            mx = fmaxf(mx, __shfl_xor_sync(0xffffffffu, mx, 2));
            float se = 0.f, sw = 0.f;
            #pragma unroll
            for (int ni = 0; ni < 8; ni++){
                #pragma unroll
                for (int e = 0; e < 2; e++){
                    int n = ni*8 + cb + e;
                    float f = acc[ni][rh*2+e];
                    float fv = (n < len) ? f : -3.0e38f;
                    float ex = __expf(fv - mx);     // exactly 0 for invalid n
                    se += ex;
                    sw = fmaf(ex, f, sw);
                }
            }
            se += __shfl_xor_sync(0xffffffffu, se, 1);
            sw += __shfl_xor_sync(0xffffffffu, sw, 1);
            se += __shfl_xor_sync(0xffffffffu, se, 2);
            sw += __shfl_xor_sync(0xffffffffu, sw, 2);
            if ((lane & 3) == 0){
                int v = t*128 + r0 + (lane >> 2) + rh*8;
                if (v < VM1) out[(size_t)b*VM1 + v] = sw/se + (rh ? ad8 : ad0);
            }
        }
    }
}

// ---------------- host side ----------------
static float* symaddr(const void* sym){
    void* p = nullptr;
    cudaGetSymbolAddress(&p, sym);
    return (float*)p;
}

extern "C" void kernel_launch(void* const* d_in, const int* in_sizes, int n_in,
                              void* d_out, int out_size){
    (void)in_sizes; (void)n_in; (void)out_size;
    const int*   items  = (const int*)  d_in[0];
    const float* A      = (const float*)d_in[1];
    const int*   mask   = (const int*)  d_in[2];
    const float* emb    = (const float*)d_in[3];
    const float* w_ih   = (const float*)d_in[4];
    const float* w_hh   = (const float*)d_in[5];
    const float* b_ih   = (const float*)d_in[6];
    const float* b_hh   = (const float*)d_in[7];
    const float* b_iah  = (const float*)d_in[8];
    const float* b_oah  = (const float*)d_in[9];
    const float* W_ein  = (const float*)d_in[10];
    const float* b_ein  = (const float*)d_in[11];
    const float* W_eout = (const float*)d_in[12];
    const float* b_eout = (const float*)d_in[13];
    const float* W_one  = (const float*)d_in[14];
    const float* b_one  = (const float*)d_in[15];
    const float* W_two  = (const float*)d_in[16];
    const float* b_two  = (const float*)d_in[17];
    const float* w_three= (const float*)d_in[18];
    const float* W_tr   = (const float*)d_in[19];
    const float* b_tr   = (const float*)d_in[20];
    const float* W_t    = (const float*)d_in[21];
    float* out = (float*)d_out;

    float* Xcat = symaddr(g_Xcat);
    float* Wcat = symaddr(g_Wcat);
    float* bc   = symaddr(g_bc);
    float* hid  = symaddr(g_hidden);
    float* q2qt = symaddr(g_q2qt);

    static int init_done = 0;
    if (!init_done){
        cudaFuncSetAttribute(k_scores_mma, cudaFuncAttributeMaxDynamicSharedMemorySize, SC_BYTES);
        init_done = 1;
    }

    // one-time preps (serial, single stream — measured fastest)
    {
        dim3 g(2, 6);
        k_prep_wa<<<g, 256>>>(w_ih, W_ein, W_eout);
    }
    k_prep_wcat2<<<512, 128>>>(w_ih, w_hh, b_ih, b_hh, b_ein, b_eout, b_iah, b_oah);
    k_prep_emb<<<NT_, 256>>>(emb);
    k_gather<<<R_, H_>>>(items, emb, A);

    // 2 GNN steps: prop2 -> gate-fused GEMM (writes g_hidden directly)
    for (int step = 0; step < 2; step++){
        k_prop2<<<R_, H_>>>(A);
        dim3 gt(8, 7);
        k_gemm_f<<<gt, 256>>>(Xcat, Wcat, Wcat, 512, bc, nullptr, nullptr, R_, KX, 512, 1);
    }

    // attention head: one GEMM produces [q2 | qt]
    {
        dim3 gq(4, 7);
        k_gemm_f<<<gq, 256>>>(hid, W_two, W_t, 128, b_two, nullptr, q2qt, R_, H_, 256, 0);
    }
    k_alpha2<<<B_, H_>>>(mask, w_three, W_one, b_one, W_tr, b_tr);

    // HMMA vocab scoring
    k_scores_mma<<<NT_, 256, SC_BYTES>>>(out);
}